// round 1
// baseline (speedup 1.0000x reference)
#include <cuda_runtime.h>
#include <math.h>

#define BSZ 16
#define SEQ 2048
#define DIM 1024
#define HD  128
#define BQ  64
#define BK  64

// Scratch for Q, K, V projections (16 MB each) — __device__ globals per the
// no-allocation rule.
__device__ float g_q[BSZ * SEQ * HD];
__device__ float g_k[BSZ * SEQ * HD];
__device__ float g_v[BSZ * SEQ * HD];

// ---------------------------------------------------------------------------
// Projection GEMM: C = X[M,K] * W[K,N], M = BSZ*SEQ = 32768, K = 1024, N = 128.
// blockIdx.z selects (Wq -> g_q), (Wk -> g_k), (Wv -> g_v).
// Tile 128(M) x 128(N), K-step 16. 256 threads, 8x8 outputs per thread.
// ---------------------------------------------------------------------------
__global__ __launch_bounds__(256, 2)
void proj_kernel(const float* __restrict__ X,
                 const float* __restrict__ Wq,
                 const float* __restrict__ Wk,
                 const float* __restrict__ Wv)
{
    __shared__ float As[16][132];   // A tile transposed: As[k][m]
    __shared__ float Bs[16][132];   // B tile: Bs[k][n]

    const int z = blockIdx.z;
    const float* __restrict__ W = (z == 0) ? Wq : ((z == 1) ? Wk : Wv);
    float* __restrict__ C       = (z == 0) ? g_q : ((z == 1) ? g_k : g_v);

    const int m0  = blockIdx.y * 128;
    const int tid = threadIdx.x;
    const int ty  = tid >> 4;     // 0..15
    const int tx  = tid & 15;     // 0..15

    float acc[8][8];
#pragma unroll
    for (int i = 0; i < 8; i++)
#pragma unroll
        for (int j = 0; j < 8; j++) acc[i][j] = 0.f;

    for (int k0 = 0; k0 < DIM; k0 += 16) {
        // Load A tile: 128 rows x 16 k. 512 float4 / 256 threads = 2 each.
#pragma unroll
        for (int t = 0; t < 2; t++) {
            int idx = t * 256 + tid;          // 0..511
            int row = idx >> 2;               // 0..127
            int kq  = (idx & 3) * 4;          // 0,4,8,12
            float4 v = *(const float4*)&X[(size_t)(m0 + row) * DIM + k0 + kq];
            As[kq + 0][row] = v.x;
            As[kq + 1][row] = v.y;
            As[kq + 2][row] = v.z;
            As[kq + 3][row] = v.w;
        }
        // Load B tile: 16 k x 128 n.
#pragma unroll
        for (int t = 0; t < 2; t++) {
            int idx = t * 256 + tid;          // 0..511
            int row = idx >> 5;               // 0..15
            int col = (idx & 31) * 4;         // 0..124
            float4 v = *(const float4*)&W[(size_t)(k0 + row) * HD + col];
            *(float4*)&Bs[row][col] = v;
        }
        __syncthreads();

#pragma unroll
        for (int kk = 0; kk < 16; kk++) {
            float a[8], b[8];
            *(float4*)&a[0] = *(const float4*)&As[kk][ty * 8];
            *(float4*)&a[4] = *(const float4*)&As[kk][ty * 8 + 4];
            *(float4*)&b[0] = *(const float4*)&Bs[kk][tx * 8];
            *(float4*)&b[4] = *(const float4*)&Bs[kk][tx * 8 + 4];
#pragma unroll
            for (int i = 0; i < 8; i++)
#pragma unroll
                for (int j = 0; j < 8; j++)
                    acc[i][j] = fmaf(a[i], b[j], acc[i][j]);
        }
        __syncthreads();
    }

#pragma unroll
    for (int i = 0; i < 8; i++) {
        size_t row = (size_t)(m0 + ty * 8 + i);
        *(float4*)&C[row * HD + tx * 8]     = *(float4*)&acc[i][0];
        *(float4*)&C[row * HD + tx * 8 + 4] = *(float4*)&acc[i][4];
    }
}

// ---------------------------------------------------------------------------
// Flash attention (causal), fp32, online softmax.
// Grid: (S/BQ = 32, B = 16). 256 threads.
// Thread (ty,tx): score tile rows ty*4+i, cols tx+16*jj ; O cols tx*8+j.
// smem: Qs 64x128 | Ks 64x128 (float4 XOR-swizzled) | Vs 64x128 | Ps 64x64
// ---------------------------------------------------------------------------
#define SMEM_ATTN ((BQ*HD + BK*HD + BK*HD + BQ*BK) * 4)

__global__ __launch_bounds__(256, 2)
void attn_kernel(float* __restrict__ out)
{
    extern __shared__ float sm[];
    float* Qs = sm;                    // 8192 floats
    float* Ks = Qs + BQ * HD;          // 8192 floats (swizzled)
    float* Vs = Ks + BK * HD;          // 8192 floats
    float* Ps = Vs + BK * HD;          // 4096 floats

    const int qt  = gridDim.x - 1 - blockIdx.x;   // heavy tiles first
    const int b   = blockIdx.y;
    const int tid = threadIdx.x;
    const int ty  = tid >> 4;
    const int tx  = tid & 15;
    const float scale = 0.08838834764831845f;     // 1/sqrt(128)

    // Load pre-scaled Q tile.
    const float* __restrict__ Qg = g_q + ((size_t)b * SEQ + qt * BQ) * HD;
#pragma unroll
    for (int t = 0; t < 8; t++) {
        int idx = t * 256 + tid;                  // float4 index 0..2047
        float4 v = *(const float4*)&Qg[idx * 4];
        v.x *= scale; v.y *= scale; v.z *= scale; v.w *= scale;
        *(float4*)&Qs[idx * 4] = v;
    }

    float m_i[4], l_i[4], o[4][8];
#pragma unroll
    for (int i = 0; i < 4; i++) {
        m_i[i] = -1e30f; l_i[i] = 0.f;
#pragma unroll
        for (int j = 0; j < 8; j++) o[i][j] = 0.f;
    }

    for (int j = 0; j <= qt; j++) {
        const float* __restrict__ Kg = g_k + ((size_t)b * SEQ + j * BK) * HD;
        const float* __restrict__ Vg = g_v + ((size_t)b * SEQ + j * BK) * HD;

        __syncthreads();   // previous iteration's Vs/Ps reads done
#pragma unroll
        for (int t = 0; t < 8; t++) {
            int idx = t * 256 + tid;              // float4 index 0..2047
            int c   = idx >> 5;                   // kv row 0..63
            int k4  = idx & 31;                   // float4 chunk 0..31
            float4 kv = *(const float4*)&Kg[idx * 4];
            int sk = (k4 & ~7) | ((k4 ^ c) & 7);  // XOR swizzle (low 3 bits)
            *(float4*)&Ks[(c << 7) + sk * 4] = kv;
            float4 vv = *(const float4*)&Vg[idx * 4];
            *(float4*)&Vs[idx * 4] = vv;
        }
        __syncthreads();

        // ---- S = (Q*scale) . K^T  (64x64 tile, 4x4 per thread) ----
        float s[4][4];
#pragma unroll
        for (int i = 0; i < 4; i++)
#pragma unroll
            for (int jj = 0; jj < 4; jj++) s[i][jj] = 0.f;

#pragma unroll 4
        for (int k4 = 0; k4 < 32; k4++) {
            float4 qv[4], kv[4];
#pragma unroll
            for (int i = 0; i < 4; i++)
                qv[i] = *(const float4*)&Qs[(ty * 4 + i) * HD + k4 * 4];
#pragma unroll
            for (int jj = 0; jj < 4; jj++) {
                int c  = tx + jj * 16;
                int sk = (k4 & ~7) | ((k4 ^ c) & 7);
                kv[jj] = *(const float4*)&Ks[(c << 7) + sk * 4];
            }
#pragma unroll
            for (int i = 0; i < 4; i++)
#pragma unroll
                for (int jj = 0; jj < 4; jj++) {
                    s[i][jj] = fmaf(qv[i].x, kv[jj].x, s[i][jj]);
                    s[i][jj] = fmaf(qv[i].y, kv[jj].y, s[i][jj]);
                    s[i][jj] = fmaf(qv[i].z, kv[jj].z, s[i][jj]);
                    s[i][jj] = fmaf(qv[i].w, kv[jj].w, s[i][jj]);
                }
        }

        // ---- causal mask on the diagonal tile ----
        if (j == qt) {
#pragma unroll
            for (int i = 0; i < 4; i++) {
                int r = ty * 4 + i;
#pragma unroll
                for (int jj = 0; jj < 4; jj++)
                    if (tx + jj * 16 > r) s[i][jj] = -1e30f;
            }
        }

        // ---- online softmax update ----
#pragma unroll
        for (int i = 0; i < 4; i++) {
            float mx = fmaxf(fmaxf(s[i][0], s[i][1]), fmaxf(s[i][2], s[i][3]));
#pragma unroll
            for (int off = 1; off < 16; off <<= 1)
                mx = fmaxf(mx, __shfl_xor_sync(0xffffffffu, mx, off));
            float mnew  = fmaxf(m_i[i], mx);
            float alpha = __expf(m_i[i] - mnew);
            float rs = 0.f;
#pragma unroll
            for (int jj = 0; jj < 4; jj++) {
                float p = __expf(s[i][jj] - mnew);
                s[i][jj] = p;
                rs += p;
            }
#pragma unroll
            for (int off = 1; off < 16; off <<= 1)
                rs += __shfl_xor_sync(0xffffffffu, rs, off);
            l_i[i] = l_i[i] * alpha + rs;
            m_i[i] = mnew;
#pragma unroll
            for (int jj = 0; jj < 8; jj++) o[i][jj] *= alpha;
        }

        // ---- stage P to smem ----
#pragma unroll
        for (int i = 0; i < 4; i++) {
            int r = ty * 4 + i;
#pragma unroll
            for (int jj = 0; jj < 4; jj++)
                Ps[r * BK + tx + jj * 16] = s[i][jj];
        }
        __syncthreads();

        // ---- O += P * V  (64x128 tile, 4x8 per thread) ----
#pragma unroll 2
        for (int kc4 = 0; kc4 < 16; kc4++) {
            float4 p4[4];
#pragma unroll
            for (int i = 0; i < 4; i++)
                p4[i] = *(const float4*)&Ps[(ty * 4 + i) * BK + kc4 * 4];
#pragma unroll
            for (int u = 0; u < 4; u++) {
                int kc = kc4 * 4 + u;
                float4 v0 = *(const float4*)&Vs[kc * HD + tx * 8];
                float4 v1 = *(const float4*)&Vs[kc * HD + tx * 8 + 4];
#pragma unroll
                for (int i = 0; i < 4; i++) {
                    float p = ((const float*)&p4[i])[u];
                    o[i][0] = fmaf(p, v0.x, o[i][0]);
                    o[i][1] = fmaf(p, v0.y, o[i][1]);
                    o[i][2] = fmaf(p, v0.z, o[i][2]);
                    o[i][3] = fmaf(p, v0.w, o[i][3]);
                    o[i][4] = fmaf(p, v1.x, o[i][4]);
                    o[i][5] = fmaf(p, v1.y, o[i][5]);
                    o[i][6] = fmaf(p, v1.z, o[i][6]);
                    o[i][7] = fmaf(p, v1.w, o[i][7]);
                }
            }
        }
    }

    // ---- normalize and store ----
#pragma unroll
    for (int i = 0; i < 4; i++) {
        size_t row = (size_t)b * SEQ + qt * BQ + ty * 4 + i;
        float inv = 1.f / l_i[i];
        float4 r0, r1;
        r0.x = o[i][0] * inv; r0.y = o[i][1] * inv;
        r0.z = o[i][2] * inv; r0.w = o[i][3] * inv;
        r1.x = o[i][4] * inv; r1.y = o[i][5] * inv;
        r1.z = o[i][6] * inv; r1.w = o[i][7] * inv;
        *(float4*)&out[row * HD + tx * 8]     = r0;
        *(float4*)&out[row * HD + tx * 8 + 4] = r1;
    }
}

// ---------------------------------------------------------------------------
extern "C" void kernel_launch(void* const* d_in, const int* in_sizes, int n_in,
                              void* d_out, int out_size)
{
    const float* x  = (const float*)d_in[0];
    const float* wq = (const float*)d_in[1];
    const float* wk = (const float*)d_in[2];
    const float* wv = (const float*)d_in[3];
    float* out = (float*)d_out;

    // Idempotent, non-stream call; safe under graph capture.
    cudaFuncSetAttribute(attn_kernel,
                         cudaFuncAttributeMaxDynamicSharedMemorySize, SMEM_ATTN);

    dim3 gridP(1, (BSZ * SEQ) / 128, 3);
    proj_kernel<<<gridP, 256>>>(x, wq, wk, wv);

    dim3 gridA(SEQ / BQ, BSZ);
    attn_kernel<<<gridA, 256, SMEM_ATTN>>>(out);
}

// round 3
// speedup vs baseline: 1.1270x; 1.1270x over previous
#include <cuda_runtime.h>
#include <math.h>
#include <cstdint>

#define BSZ 16
#define SEQ 2048
#define DIM 1024
#define HD  128
#define BQ  64
#define BK  64

// Scratch for Q, K, V projections — __device__ globals per the no-allocation rule.
__device__ float g_q[BSZ * SEQ * HD];
__device__ float g_k[BSZ * SEQ * HD];
__device__ float g_v[BSZ * SEQ * HD];

// ---------------------------------------------------------------------------
// Helpers: cp.async, tf32 convert, mma.sync (all sm_80+ features — no 'a' ISA)
// ---------------------------------------------------------------------------
__device__ __forceinline__ uint32_t smem_u32(const void* p) {
    uint32_t a;
    asm("{ .reg .u64 t; cvta.to.shared.u64 t, %1; cvt.u32.u64 %0, t; }" : "=r"(a) : "l"(p));
    return a;
}

__device__ __forceinline__ void cp16(uint32_t dst, const void* src) {
    asm volatile("cp.async.cg.shared.global [%0], [%1], 16;" :: "r"(dst), "l"(src));
}
#define CP_COMMIT() asm volatile("cp.async.commit_group;" ::: "memory")
template <int N>
__device__ __forceinline__ void cp_wait() {
    asm volatile("cp.async.wait_group %0;" :: "n"(N) : "memory");
}

__device__ __forceinline__ uint32_t f2tf32(float x) {
    uint32_t r;
    asm("cvt.rna.tf32.f32 %0, %1;" : "=r"(r) : "f"(x));
    return r;
}

__device__ __forceinline__ void mma_tf32(float* c, const uint32_t* a, const uint32_t* b) {
    asm volatile(
        "mma.sync.aligned.m16n8k8.row.col.f32.tf32.tf32.f32 "
        "{%0,%1,%2,%3}, {%4,%5,%6,%7}, {%8,%9}, {%0,%1,%2,%3};"
        : "+f"(c[0]), "+f"(c[1]), "+f"(c[2]), "+f"(c[3])
        : "r"(a[0]), "r"(a[1]), "r"(a[2]), "r"(a[3]), "r"(b[0]), "r"(b[1]));
}

// ---------------------------------------------------------------------------
// Projection GEMM via mma.sync tf32 + 3xTF32 compensation.
// C[32768,128] = X[32768,1024] * W[1024,128].  blockIdx.y = z in {q,k,v}.
// CTA: 256 thr (8 warps, 4M x 2N), tile M=128 N=128, K-step 32, 2-stage cp.async.
// Smem (raw fp32): A[128][36] per stage (18432 B), B[32][136] per stage (17408 B).
// Fragment LDS conflict-free by stride choice (A: 36 -> bank 4g+tg; B: 136 -> 8tg+g).
// ---------------------------------------------------------------------------
#define A_STRIDE 36
#define B_STRIDE 136
#define A_STAGE_B 18432                  // 128*36*4
#define B_STAGE_B 17408                  // 32*136*4
#define B_BASE_B  (2 * A_STAGE_B)        // 36864
#define PROJ_SMEM (2 * A_STAGE_B + 2 * B_STAGE_B)   // 71680
#define PROJ_NT   (DIM / 32)             // 32 k-tiles

__global__ __launch_bounds__(256, 1)
void proj_mma_kernel(const float* __restrict__ X,
                     const float* __restrict__ Wq,
                     const float* __restrict__ Wk,
                     const float* __restrict__ Wv)
{
    extern __shared__ float smf[];
    const uint32_t sbase = smem_u32(smf);
    const int tid  = threadIdx.x;
    const int wid  = tid >> 5;
    const int lane = tid & 31;
    const int g    = lane >> 2;          // 0..7
    const int tg   = lane & 3;           // 0..3
    const int wm   = wid >> 1;           // warp M index 0..3
    const int wn   = wid & 1;            // warp N index 0..1
    const int z    = blockIdx.y;
    const int m0   = blockIdx.x * 128;

    const float* __restrict__ W = (z == 0) ? Wq : ((z == 1) ? Wk : Wv);
    float* __restrict__ C       = (z == 0) ? g_q : ((z == 1) ? g_k : g_v);

    float acc[2][8][4];
#pragma unroll
    for (int mf = 0; mf < 2; mf++)
#pragma unroll
        for (int nf = 0; nf < 8; nf++)
#pragma unroll
            for (int r = 0; r < 4; r++) acc[mf][nf][r] = 0.f;

    // ---- stage lambda-equivalent (macro-free, inlined twice) ----
    auto stage = [&](int s, int t) {
        const int k0 = t * 32;
        // A tile: 128 rows x 32 floats = 1024 x 16B chunks, 4 per thread.
#pragma unroll
        for (int q = 0; q < 4; q++) {
            int c   = q * 256 + tid;
            int row = c >> 3;
            int ch  = c & 7;
            cp16(sbase + s * A_STAGE_B + row * (A_STRIDE * 4) + ch * 16,
                 &X[(size_t)(m0 + row) * DIM + k0 + ch * 4]);
        }
        // B tile: 32 rows x 128 floats = 1024 x 16B chunks, 4 per thread.
#pragma unroll
        for (int q = 0; q < 4; q++) {
            int c   = q * 256 + tid;
            int row = c >> 5;
            int ch  = c & 31;
            cp16(sbase + B_BASE_B + s * B_STAGE_B + row * (B_STRIDE * 4) + ch * 16,
                 &W[(size_t)(k0 + row) * HD + ch * 4]);
        }
        CP_COMMIT();
    };

    stage(0, 0);

    for (int t = 0; t < PROJ_NT; t++) {
        const int s = t & 1;
        if (t + 1 < PROJ_NT) {
            stage(s ^ 1, t + 1);
            cp_wait<1>();
        } else {
            cp_wait<0>();
        }
        __syncthreads();

        const float* As = smf + s * (A_STAGE_B / 4);
        const float* Bs = smf + (B_BASE_B / 4) + s * (B_STAGE_B / 4);

#pragma unroll
        for (int sub = 0; sub < 4; sub++) {
            const int k8 = sub * 8;

            // A fragments (raw fp32) -> hi/lo tf32
            uint32_t ah[2][4], al[2][4];
#pragma unroll
            for (int mf = 0; mf < 2; mf++) {
                const int r = wm * 32 + mf * 16 + g;
                float a0 = As[r * A_STRIDE + k8 + tg];
                float a1 = As[(r + 8) * A_STRIDE + k8 + tg];
                float a2 = As[r * A_STRIDE + k8 + tg + 4];
                float a3 = As[(r + 8) * A_STRIDE + k8 + tg + 4];
                ah[mf][0] = f2tf32(a0); al[mf][0] = f2tf32(a0 - __uint_as_float(ah[mf][0]));
                ah[mf][1] = f2tf32(a1); al[mf][1] = f2tf32(a1 - __uint_as_float(ah[mf][1]));
                ah[mf][2] = f2tf32(a2); al[mf][2] = f2tf32(a2 - __uint_as_float(ah[mf][2]));
                ah[mf][3] = f2tf32(a3); al[mf][3] = f2tf32(a3 - __uint_as_float(ah[mf][3]));
            }

            // B fragments
            uint32_t bh[8][2], bl[8][2];
#pragma unroll
            for (int nf = 0; nf < 8; nf++) {
                const int n = wn * 64 + nf * 8 + g;
                float b0 = Bs[(k8 + tg) * B_STRIDE + n];
                float b1 = Bs[(k8 + tg + 4) * B_STRIDE + n];
                bh[nf][0] = f2tf32(b0); bl[nf][0] = f2tf32(b0 - __uint_as_float(bh[nf][0]));
                bh[nf][1] = f2tf32(b1); bl[nf][1] = f2tf32(b1 - __uint_as_float(bh[nf][1]));
            }

            // 3xTF32: hi*hi + lo*hi + hi*lo
#pragma unroll
            for (int mf = 0; mf < 2; mf++)
#pragma unroll
                for (int nf = 0; nf < 8; nf++) {
                    mma_tf32(acc[mf][nf], ah[mf], bh[nf]);
                    mma_tf32(acc[mf][nf], al[mf], bh[nf]);
                    mma_tf32(acc[mf][nf], ah[mf], bl[nf]);
                }
        }
        __syncthreads();
    }

    // Epilogue: c0,c1 at (row, col..col+1); c2,c3 at (row+8, ...)
#pragma unroll
    for (int mf = 0; mf < 2; mf++) {
        const int row = m0 + wm * 32 + mf * 16 + g;
#pragma unroll
        for (int nf = 0; nf < 8; nf++) {
            const int col = wn * 64 + nf * 8 + tg * 2;
            *(float2*)&C[(size_t)row * HD + col]       = make_float2(acc[mf][nf][0], acc[mf][nf][1]);
            *(float2*)&C[(size_t)(row + 8) * HD + col] = make_float2(acc[mf][nf][2], acc[mf][nf][3]);
        }
    }
}

// ---------------------------------------------------------------------------
// Flash attention (causal), fp32, online softmax.  (unchanged from R1 pass)
// ---------------------------------------------------------------------------
#define SMEM_ATTN ((BQ*HD + BK*HD + BK*HD + BQ*BK) * 4)

__global__ __launch_bounds__(256, 2)
void attn_kernel(float* __restrict__ out)
{
    extern __shared__ float sm[];
    float* Qs = sm;                    // 8192 floats
    float* Ks = Qs + BQ * HD;          // 8192 floats (swizzled)
    float* Vs = Ks + BK * HD;          // 8192 floats
    float* Ps = Vs + BK * HD;          // 4096 floats

    const int qt  = gridDim.x - 1 - blockIdx.x;   // heavy tiles first
    const int b   = blockIdx.y;
    const int tid = threadIdx.x;
    const int ty  = tid >> 4;
    const int tx  = tid & 15;
    const float scale = 0.08838834764831845f;     // 1/sqrt(128)

    const float* __restrict__ Qg = g_q + ((size_t)b * SEQ + qt * BQ) * HD;
#pragma unroll
    for (int t = 0; t < 8; t++) {
        int idx = t * 256 + tid;
        float4 v = *(const float4*)&Qg[idx * 4];
        v.x *= scale; v.y *= scale; v.z *= scale; v.w *= scale;
        *(float4*)&Qs[idx * 4] = v;
    }

    float m_i[4], l_i[4], o[4][8];
#pragma unroll
    for (int i = 0; i < 4; i++) {
        m_i[i] = -1e30f; l_i[i] = 0.f;
#pragma unroll
        for (int j = 0; j < 8; j++) o[i][j] = 0.f;
    }

    for (int j = 0; j <= qt; j++) {
        const float* __restrict__ Kg = g_k + ((size_t)b * SEQ + j * BK) * HD;
        const float* __restrict__ Vg = g_v + ((size_t)b * SEQ + j * BK) * HD;

        __syncthreads();
#pragma unroll
        for (int t = 0; t < 8; t++) {
            int idx = t * 256 + tid;
            int c   = idx >> 5;
            int k4  = idx & 31;
            float4 kv = *(const float4*)&Kg[idx * 4];
            int sk = (k4 & ~7) | ((k4 ^ c) & 7);
            *(float4*)&Ks[(c << 7) + sk * 4] = kv;
            float4 vv = *(const float4*)&Vg[idx * 4];
            *(float4*)&Vs[idx * 4] = vv;
        }
        __syncthreads();

        float s[4][4];
#pragma unroll
        for (int i = 0; i < 4; i++)
#pragma unroll
            for (int jj = 0; jj < 4; jj++) s[i][jj] = 0.f;

#pragma unroll 4
        for (int k4 = 0; k4 < 32; k4++) {
            float4 qv[4], kv[4];
#pragma unroll
            for (int i = 0; i < 4; i++)
                qv[i] = *(const float4*)&Qs[(ty * 4 + i) * HD + k4 * 4];
#pragma unroll
            for (int jj = 0; jj < 4; jj++) {
                int c  = tx + jj * 16;
                int sk = (k4 & ~7) | ((k4 ^ c) & 7);
                kv[jj] = *(const float4*)&Ks[(c << 7) + sk * 4];
            }
#pragma unroll
            for (int i = 0; i < 4; i++)
#pragma unroll
                for (int jj = 0; jj < 4; jj++) {
                    s[i][jj] = fmaf(qv[i].x, kv[jj].x, s[i][jj]);
                    s[i][jj] = fmaf(qv[i].y, kv[jj].y, s[i][jj]);
                    s[i][jj] = fmaf(qv[i].z, kv[jj].z, s[i][jj]);
                    s[i][jj] = fmaf(qv[i].w, kv[jj].w, s[i][jj]);
                }
        }

        if (j == qt) {
#pragma unroll
            for (int i = 0; i < 4; i++) {
                int r = ty * 4 + i;
#pragma unroll
                for (int jj = 0; jj < 4; jj++)
                    if (tx + jj * 16 > r) s[i][jj] = -1e30f;
            }
        }

#pragma unroll
        for (int i = 0; i < 4; i++) {
            float mx = fmaxf(fmaxf(s[i][0], s[i][1]), fmaxf(s[i][2], s[i][3]));
#pragma unroll
            for (int off = 1; off < 16; off <<= 1)
                mx = fmaxf(mx, __shfl_xor_sync(0xffffffffu, mx, off));
            float mnew  = fmaxf(m_i[i], mx);
            float alpha = __expf(m_i[i] - mnew);
            float rs = 0.f;
#pragma unroll
            for (int jj = 0; jj < 4; jj++) {
                float p = __expf(s[i][jj] - mnew);
                s[i][jj] = p;
                rs += p;
            }
#pragma unroll
            for (int off = 1; off < 16; off <<= 1)
                rs += __shfl_xor_sync(0xffffffffu, rs, off);
            l_i[i] = l_i[i] * alpha + rs;
            m_i[i] = mnew;
#pragma unroll
            for (int jj = 0; jj < 8; jj++) o[i][jj] *= alpha;
        }

#pragma unroll
        for (int i = 0; i < 4; i++) {
            int r = ty * 4 + i;
#pragma unroll
            for (int jj = 0; jj < 4; jj++)
                Ps[r * BK + tx + jj * 16] = s[i][jj];
        }
        __syncthreads();

#pragma unroll 2
        for (int kc4 = 0; kc4 < 16; kc4++) {
            float4 p4[4];
#pragma unroll
            for (int i = 0; i < 4; i++)
                p4[i] = *(const float4*)&Ps[(ty * 4 + i) * BK + kc4 * 4];
#pragma unroll
            for (int u = 0; u < 4; u++) {
                int kc = kc4 * 4 + u;
                float4 v0 = *(const float4*)&Vs[kc * HD + tx * 8];
                float4 v1 = *(const float4*)&Vs[kc * HD + tx * 8 + 4];
#pragma unroll
                for (int i = 0; i < 4; i++) {
                    float p = ((const float*)&p4[i])[u];
                    o[i][0] = fmaf(p, v0.x, o[i][0]);
                    o[i][1] = fmaf(p, v0.y, o[i][1]);
                    o[i][2] = fmaf(p, v0.z, o[i][2]);
                    o[i][3] = fmaf(p, v0.w, o[i][3]);
                    o[i][4] = fmaf(p, v1.x, o[i][4]);
                    o[i][5] = fmaf(p, v1.y, o[i][5]);
                    o[i][6] = fmaf(p, v1.z, o[i][6]);
                    o[i][7] = fmaf(p, v1.w, o[i][7]);
                }
            }
        }
    }

#pragma unroll
    for (int i = 0; i < 4; i++) {
        size_t row = (size_t)b * SEQ + qt * BQ + ty * 4 + i;
        float inv = 1.f / l_i[i];
        float4 r0, r1;
        r0.x = o[i][0] * inv; r0.y = o[i][1] * inv;
        r0.z = o[i][2] * inv; r0.w = o[i][3] * inv;
        r1.x = o[i][4] * inv; r1.y = o[i][5] * inv;
        r1.z = o[i][6] * inv; r1.w = o[i][7] * inv;
        *(float4*)&out[row * HD + tx * 8]     = r0;
        *(float4*)&out[row * HD + tx * 8 + 4] = r1;
    }
}

// ---------------------------------------------------------------------------
extern "C" void kernel_launch(void* const* d_in, const int* in_sizes, int n_in,
                              void* d_out, int out_size)
{
    const float* x  = (const float*)d_in[0];
    const float* wq = (const float*)d_in[1];
    const float* wk = (const float*)d_in[2];
    const float* wv = (const float*)d_in[3];
    float* out = (float*)d_out;

    cudaFuncSetAttribute(proj_mma_kernel,
                         cudaFuncAttributeMaxDynamicSharedMemorySize, PROJ_SMEM);
    cudaFuncSetAttribute(attn_kernel,
                         cudaFuncAttributeMaxDynamicSharedMemorySize, SMEM_ATTN);

    dim3 gridP((BSZ * SEQ) / 128, 3);
    proj_mma_kernel<<<gridP, 256, PROJ_SMEM>>>(x, wq, wk, wv);

    dim3 gridA(SEQ / BQ, BSZ);
    attn_kernel<<<gridA, 256, SMEM_ATTN>>>(out);
}

// round 4
// speedup vs baseline: 1.2880x; 1.1429x over previous
#include <cuda_runtime.h>
#include <math.h>
#include <cstdint>

#define BSZ 16
#define SEQ 2048
#define DIM 1024
#define HD  128

// Scratch for Q, K, V projections — __device__ globals per the no-allocation rule.
__device__ float g_q[BSZ * SEQ * HD];
__device__ float g_k[BSZ * SEQ * HD];
__device__ float g_v[BSZ * SEQ * HD];

// ---------------------------------------------------------------------------
// Helpers: cp.async, tf32 convert, mma.sync (sm_80+ features only)
// ---------------------------------------------------------------------------
__device__ __forceinline__ uint32_t smem_u32(const void* p) {
    uint32_t a;
    asm("{ .reg .u64 t; cvta.to.shared.u64 t, %1; cvt.u32.u64 %0, t; }" : "=r"(a) : "l"(p));
    return a;
}

__device__ __forceinline__ void cp16(uint32_t dst, const void* src) {
    asm volatile("cp.async.cg.shared.global [%0], [%1], 16;" :: "r"(dst), "l"(src));
}
#define CP_COMMIT() asm volatile("cp.async.commit_group;" ::: "memory")
template <int N>
__device__ __forceinline__ void cp_wait() {
    asm volatile("cp.async.wait_group %0;" :: "n"(N) : "memory");
}

__device__ __forceinline__ uint32_t f2tf32(float x) {
    uint32_t r;
    asm("cvt.rna.tf32.f32 %0, %1;" : "=r"(r) : "f"(x));
    return r;
}

__device__ __forceinline__ void mma_tf32(float* c, const uint32_t* a, const uint32_t* b) {
    asm volatile(
        "mma.sync.aligned.m16n8k8.row.col.f32.tf32.tf32.f32 "
        "{%0,%1,%2,%3}, {%4,%5,%6,%7}, {%8,%9}, {%0,%1,%2,%3};"
        : "+f"(c[0]), "+f"(c[1]), "+f"(c[2]), "+f"(c[3])
        : "r"(a[0]), "r"(a[1]), "r"(a[2]), "r"(a[3]), "r"(b[0]), "r"(b[1]));
}

// Split a raw fp32 fragment into tf32 hi + lo
__device__ __forceinline__ void split2(float x, uint32_t& h, uint32_t& l) {
    h = f2tf32(x);
    l = f2tf32(x - __uint_as_float(h));
}

// ---------------------------------------------------------------------------
// Projection GEMM via mma.sync tf32 + 3xTF32 compensation. (unchanged, passing)
// ---------------------------------------------------------------------------
#define A_STRIDE 36
#define B_STRIDE 136
#define A_STAGE_B 18432
#define B_STAGE_B 17408
#define B_BASE_B  (2 * A_STAGE_B)
#define PROJ_SMEM (2 * A_STAGE_B + 2 * B_STAGE_B)
#define PROJ_NT   (DIM / 32)

__global__ __launch_bounds__(256, 1)
void proj_mma_kernel(const float* __restrict__ X,
                     const float* __restrict__ Wq,
                     const float* __restrict__ Wk,
                     const float* __restrict__ Wv)
{
    extern __shared__ float smf[];
    const uint32_t sbase = smem_u32(smf);
    const int tid  = threadIdx.x;
    const int wid  = tid >> 5;
    const int lane = tid & 31;
    const int g    = lane >> 2;
    const int tg   = lane & 3;
    const int wm   = wid >> 1;
    const int wn   = wid & 1;
    const int z    = blockIdx.y;
    const int m0   = blockIdx.x * 128;

    const float* __restrict__ W = (z == 0) ? Wq : ((z == 1) ? Wk : Wv);
    float* __restrict__ C       = (z == 0) ? g_q : ((z == 1) ? g_k : g_v);

    float acc[2][8][4];
#pragma unroll
    for (int mf = 0; mf < 2; mf++)
#pragma unroll
        for (int nf = 0; nf < 8; nf++)
#pragma unroll
            for (int r = 0; r < 4; r++) acc[mf][nf][r] = 0.f;

    auto stage = [&](int s, int t) {
        const int k0 = t * 32;
#pragma unroll
        for (int q = 0; q < 4; q++) {
            int c   = q * 256 + tid;
            int row = c >> 3;
            int ch  = c & 7;
            cp16(sbase + s * A_STAGE_B + row * (A_STRIDE * 4) + ch * 16,
                 &X[(size_t)(m0 + row) * DIM + k0 + ch * 4]);
        }
#pragma unroll
        for (int q = 0; q < 4; q++) {
            int c   = q * 256 + tid;
            int row = c >> 5;
            int ch  = c & 31;
            cp16(sbase + B_BASE_B + s * B_STAGE_B + row * (B_STRIDE * 4) + ch * 16,
                 &W[(size_t)(k0 + row) * HD + ch * 4]);
        }
        CP_COMMIT();
    };

    stage(0, 0);

    for (int t = 0; t < PROJ_NT; t++) {
        const int s = t & 1;
        if (t + 1 < PROJ_NT) {
            stage(s ^ 1, t + 1);
            cp_wait<1>();
        } else {
            cp_wait<0>();
        }
        __syncthreads();

        const float* As = smf + s * (A_STAGE_B / 4);
        const float* Bs = smf + (B_BASE_B / 4) + s * (B_STAGE_B / 4);

#pragma unroll
        for (int sub = 0; sub < 4; sub++) {
            const int k8 = sub * 8;
            uint32_t ah[2][4], al[2][4];
#pragma unroll
            for (int mf = 0; mf < 2; mf++) {
                const int r = wm * 32 + mf * 16 + g;
                split2(As[r * A_STRIDE + k8 + tg],           ah[mf][0], al[mf][0]);
                split2(As[(r + 8) * A_STRIDE + k8 + tg],     ah[mf][1], al[mf][1]);
                split2(As[r * A_STRIDE + k8 + tg + 4],       ah[mf][2], al[mf][2]);
                split2(As[(r + 8) * A_STRIDE + k8 + tg + 4], ah[mf][3], al[mf][3]);
            }
            uint32_t bh[8][2], bl[8][2];
#pragma unroll
            for (int nf = 0; nf < 8; nf++) {
                const int n = wn * 64 + nf * 8 + g;
                split2(Bs[(k8 + tg) * B_STRIDE + n],     bh[nf][0], bl[nf][0]);
                split2(Bs[(k8 + tg + 4) * B_STRIDE + n], bh[nf][1], bl[nf][1]);
            }
#pragma unroll
            for (int mf = 0; mf < 2; mf++)
#pragma unroll
                for (int nf = 0; nf < 8; nf++) {
                    mma_tf32(acc[mf][nf], ah[mf], bh[nf]);
                    mma_tf32(acc[mf][nf], al[mf], bh[nf]);
                    mma_tf32(acc[mf][nf], ah[mf], bl[nf]);
                }
        }
        __syncthreads();
    }

#pragma unroll
    for (int mf = 0; mf < 2; mf++) {
        const int row = m0 + wm * 32 + mf * 16 + g;
#pragma unroll
        for (int nf = 0; nf < 8; nf++) {
            const int col = wn * 64 + nf * 8 + tg * 2;
            *(float2*)&C[(size_t)row * HD + col]       = make_float2(acc[mf][nf][0], acc[mf][nf][1]);
            *(float2*)&C[(size_t)(row + 8) * HD + col] = make_float2(acc[mf][nf][2], acc[mf][nf][3]);
        }
    }
}

// ---------------------------------------------------------------------------
// Flash attention (causal) on mma.sync tf32 3x.
// BQ=128 q-rows per CTA, BK=64 kv per tile. 8 warps; warp w owns q-rows
// [w*16, w*16+16) — softmax rows never cross warps.
// Smem (floats): Qs[128][132] | Ks[64][132] | Vs[64][132] | Ps[128][68]
// Fragment LDS conflict-free: bank = (4*row + k) & 31 for strides 132/68.
// ---------------------------------------------------------------------------
#define ATT_BQ 128
#define ATT_BK 64
#define QSTR 132
#define PSTR 68
#define QS_OFF 0
#define KS_OFF (ATT_BQ * QSTR)                  // 16896
#define VS_OFF (KS_OFF + ATT_BK * QSTR)         // 25344
#define PS_OFF (VS_OFF + ATT_BK * QSTR)         // 33792
#define ATT_SMEM ((PS_OFF + ATT_BQ * PSTR) * 4) // 169984 B

__global__ __launch_bounds__(256, 1)
void attn_mma_kernel(float* __restrict__ out)
{
    extern __shared__ float sm[];
    float* Qs = sm + QS_OFF;
    float* Ks = sm + KS_OFF;
    float* Vs = sm + VS_OFF;
    float* Ps = sm + PS_OFF;

    const int qt   = gridDim.x - 1 - blockIdx.x;   // heavy tiles first
    const int b    = blockIdx.y;
    const int tid  = threadIdx.x;
    const int wid  = tid >> 5;
    const int lane = tid & 31;
    const int g    = lane >> 2;       // 0..7
    const int tg   = lane & 3;        // 0..3
    const int wbase = wid * 16;       // warp's q-row base within tile
    const float scale = 0.08838834764831845f;      // 1/sqrt(128)

    // ---- load Q tile (scaled) ----
    const float* __restrict__ Qg = g_q + ((size_t)b * SEQ + (size_t)qt * ATT_BQ) * HD;
#pragma unroll
    for (int t = 0; t < 16; t++) {
        int idx = t * 256 + tid;      // float4 idx over 128x128
        int row = idx >> 5;
        int c4  = (idx & 31) * 4;
        float4 v = *(const float4*)&Qg[(size_t)row * HD + c4];
        v.x *= scale; v.y *= scale; v.z *= scale; v.w *= scale;
        *(float4*)&Qs[row * QSTR + c4] = v;
    }

    float m_i[2] = {-1e30f, -1e30f};
    float l_i[2] = {0.f, 0.f};
    float o[16][4];
#pragma unroll
    for (int nf = 0; nf < 16; nf++)
#pragma unroll
        for (int r = 0; r < 4; r++) o[nf][r] = 0.f;

    const int ntiles = 2 * qt + 2;
    const int rowg   = qt * ATT_BQ + wbase + g;    // global row of this thread's row 0

    for (int j = 0; j < ntiles; j++) {
        const float* __restrict__ Kg = g_k + ((size_t)b * SEQ + (size_t)j * ATT_BK) * HD;
        const float* __restrict__ Vg = g_v + ((size_t)b * SEQ + (size_t)j * ATT_BK) * HD;

        __syncthreads();   // all warps done reading previous Ks/Vs
#pragma unroll
        for (int t = 0; t < 8; t++) {
            int idx = t * 256 + tid;  // float4 idx over 64x128
            int row = idx >> 5;
            int c4  = (idx & 31) * 4;
            *(float4*)&Ks[row * QSTR + c4] = *(const float4*)&Kg[(size_t)row * HD + c4];
            *(float4*)&Vs[row * QSTR + c4] = *(const float4*)&Vg[(size_t)row * HD + c4];
        }
        __syncthreads();

        // ---- S = Q . K^T  (warp: 16 x 64), 3xTF32 ----
        float s[8][4];
#pragma unroll
        for (int nf = 0; nf < 8; nf++)
#pragma unroll
            for (int r = 0; r < 4; r++) s[nf][r] = 0.f;

#pragma unroll
        for (int k8 = 0; k8 < 16; k8++) {
            const int k = k8 * 8;
            uint32_t ah[4], al[4];
            split2(Qs[(wbase + g) * QSTR + k + tg],         ah[0], al[0]);
            split2(Qs[(wbase + g + 8) * QSTR + k + tg],     ah[1], al[1]);
            split2(Qs[(wbase + g) * QSTR + k + tg + 4],     ah[2], al[2]);
            split2(Qs[(wbase + g + 8) * QSTR + k + tg + 4], ah[3], al[3]);
#pragma unroll
            for (int nf = 0; nf < 8; nf++) {
                uint32_t bh[2], bl[2];
                split2(Ks[(nf * 8 + g) * QSTR + k + tg],     bh[0], bl[0]);
                split2(Ks[(nf * 8 + g) * QSTR + k + tg + 4], bh[1], bl[1]);
                mma_tf32(s[nf], ah, bh);
                mma_tf32(s[nf], al, bh);
                mma_tf32(s[nf], ah, bl);
            }
        }

        // ---- causal mask (only last two tiles can be partial) ----
        if (j >= 2 * qt) {
            const int colbase = j * ATT_BK;
#pragma unroll
            for (int nf = 0; nf < 8; nf++) {
                int c0 = colbase + nf * 8 + tg * 2;
                if (c0 > rowg)          s[nf][0] = -1e30f;
                if (c0 + 1 > rowg)      s[nf][1] = -1e30f;
                if (c0 > rowg + 8)      s[nf][2] = -1e30f;
                if (c0 + 1 > rowg + 8)  s[nf][3] = -1e30f;
            }
        }

        // ---- online softmax (rows g and g+8, quad reductions) ----
        float mx0 = -1e30f, mx1 = -1e30f;
#pragma unroll
        for (int nf = 0; nf < 8; nf++) {
            mx0 = fmaxf(mx0, fmaxf(s[nf][0], s[nf][1]));
            mx1 = fmaxf(mx1, fmaxf(s[nf][2], s[nf][3]));
        }
        mx0 = fmaxf(mx0, __shfl_xor_sync(0xffffffffu, mx0, 1));
        mx0 = fmaxf(mx0, __shfl_xor_sync(0xffffffffu, mx0, 2));
        mx1 = fmaxf(mx1, __shfl_xor_sync(0xffffffffu, mx1, 1));
        mx1 = fmaxf(mx1, __shfl_xor_sync(0xffffffffu, mx1, 2));

        float mn0 = fmaxf(m_i[0], mx0);
        float mn1 = fmaxf(m_i[1], mx1);
        float al0 = __expf(m_i[0] - mn0);
        float al1 = __expf(m_i[1] - mn1);

        float rs0 = 0.f, rs1 = 0.f;
#pragma unroll
        for (int nf = 0; nf < 8; nf++) {
            s[nf][0] = __expf(s[nf][0] - mn0);
            s[nf][1] = __expf(s[nf][1] - mn0);
            s[nf][2] = __expf(s[nf][2] - mn1);
            s[nf][3] = __expf(s[nf][3] - mn1);
            rs0 += s[nf][0] + s[nf][1];
            rs1 += s[nf][2] + s[nf][3];
        }
        rs0 += __shfl_xor_sync(0xffffffffu, rs0, 1);
        rs0 += __shfl_xor_sync(0xffffffffu, rs0, 2);
        rs1 += __shfl_xor_sync(0xffffffffu, rs1, 1);
        rs1 += __shfl_xor_sync(0xffffffffu, rs1, 2);

        l_i[0] = l_i[0] * al0 + rs0;
        l_i[1] = l_i[1] * al1 + rs1;
        m_i[0] = mn0;
        m_i[1] = mn1;

#pragma unroll
        for (int nf = 0; nf < 16; nf++) {
            o[nf][0] *= al0; o[nf][1] *= al0;
            o[nf][2] *= al1; o[nf][3] *= al1;
        }

        // ---- stage P to warp-private smem rows ----
#pragma unroll
        for (int nf = 0; nf < 8; nf++) {
            *(float2*)&Ps[(wbase + g) * PSTR + nf * 8 + tg * 2]     = make_float2(s[nf][0], s[nf][1]);
            *(float2*)&Ps[(wbase + g + 8) * PSTR + nf * 8 + tg * 2] = make_float2(s[nf][2], s[nf][3]);
        }
        __syncwarp();

        // ---- O += P . V  (warp: 16 x 128), 3xTF32 ----
#pragma unroll
        for (int k8 = 0; k8 < 8; k8++) {
            const int k = k8 * 8;
            uint32_t ph[4], pl[4];
            split2(Ps[(wbase + g) * PSTR + k + tg],         ph[0], pl[0]);
            split2(Ps[(wbase + g + 8) * PSTR + k + tg],     ph[1], pl[1]);
            split2(Ps[(wbase + g) * PSTR + k + tg + 4],     ph[2], pl[2]);
            split2(Ps[(wbase + g + 8) * PSTR + k + tg + 4], ph[3], pl[3]);
#pragma unroll
            for (int nf = 0; nf < 16; nf++) {
                uint32_t vh[2], vl[2];
                split2(Vs[(k + tg) * QSTR + nf * 8 + g],     vh[0], vl[0]);
                split2(Vs[(k + tg + 4) * QSTR + nf * 8 + g], vh[1], vl[1]);
                mma_tf32(o[nf], ph, vh);
                mma_tf32(o[nf], pl, vh);
                mma_tf32(o[nf], ph, vl);
            }
        }
        __syncwarp();   // P reads done before next iteration overwrites
    }

    // ---- normalize and store ----
    const float inv0 = 1.f / l_i[0];
    const float inv1 = 1.f / l_i[1];
    const size_t row0 = (size_t)b * SEQ + (size_t)qt * ATT_BQ + wbase + g;
#pragma unroll
    for (int nf = 0; nf < 16; nf++) {
        const int col = nf * 8 + tg * 2;
        *(float2*)&out[row0 * HD + col]       = make_float2(o[nf][0] * inv0, o[nf][1] * inv0);
        *(float2*)&out[(row0 + 8) * HD + col] = make_float2(o[nf][2] * inv1, o[nf][3] * inv1);
    }
}

// ---------------------------------------------------------------------------
extern "C" void kernel_launch(void* const* d_in, const int* in_sizes, int n_in,
                              void* d_out, int out_size)
{
    const float* x  = (const float*)d_in[0];
    const float* wq = (const float*)d_in[1];
    const float* wk = (const float*)d_in[2];
    const float* wv = (const float*)d_in[3];
    float* out = (float*)d_out;

    cudaFuncSetAttribute(proj_mma_kernel,
                         cudaFuncAttributeMaxDynamicSharedMemorySize, PROJ_SMEM);
    cudaFuncSetAttribute(attn_mma_kernel,
                         cudaFuncAttributeMaxDynamicSharedMemorySize, ATT_SMEM);

    dim3 gridP((BSZ * SEQ) / 128, 3);
    proj_mma_kernel<<<gridP, 256, PROJ_SMEM>>>(x, wq, wk, wv);

    dim3 gridA(SEQ / ATT_BQ, BSZ);
    attn_mma_kernel<<<gridA, 256, ATT_SMEM>>>(out);
}

// round 5
// speedup vs baseline: 1.2887x; 1.0005x over previous
#include <cuda_runtime.h>
#include <math.h>
#include <cstdint>

#define BSZ 16
#define SEQ 2048
#define DIM 1024
#define HD  128

// Scratch for Q, K, V projections — __device__ globals per the no-allocation rule.
__device__ float g_q[BSZ * SEQ * HD];
__device__ float g_k[BSZ * SEQ * HD];
__device__ float g_v[BSZ * SEQ * HD];

// ---------------------------------------------------------------------------
// Helpers: cp.async, tf32 convert, mma.sync (sm_80+ features only)
// ---------------------------------------------------------------------------
__device__ __forceinline__ uint32_t smem_u32(const void* p) {
    uint32_t a;
    asm("{ .reg .u64 t; cvta.to.shared.u64 t, %1; cvt.u32.u64 %0, t; }" : "=r"(a) : "l"(p));
    return a;
}

__device__ __forceinline__ void cp16(uint32_t dst, const void* src) {
    asm volatile("cp.async.cg.shared.global [%0], [%1], 16;" :: "r"(dst), "l"(src));
}
#define CP_COMMIT() asm volatile("cp.async.commit_group;" ::: "memory")
template <int N>
__device__ __forceinline__ void cp_wait() {
    asm volatile("cp.async.wait_group %0;" :: "n"(N) : "memory");
}

__device__ __forceinline__ uint32_t f2tf32(float x) {
    uint32_t r;
    asm("cvt.rna.tf32.f32 %0, %1;" : "=r"(r) : "f"(x));
    return r;
}

__device__ __forceinline__ void mma_tf32(float* c, const uint32_t* a, const uint32_t* b) {
    asm volatile(
        "mma.sync.aligned.m16n8k8.row.col.f32.tf32.tf32.f32 "
        "{%0,%1,%2,%3}, {%4,%5,%6,%7}, {%8,%9}, {%0,%1,%2,%3};"
        : "+f"(c[0]), "+f"(c[1]), "+f"(c[2]), "+f"(c[3])
        : "r"(a[0]), "r"(a[1]), "r"(a[2]), "r"(a[3]), "r"(b[0]), "r"(b[1]));
}

// Split a raw fp32 fragment into tf32 hi + lo
__device__ __forceinline__ void split2(float x, uint32_t& h, uint32_t& l) {
    h = f2tf32(x);
    l = f2tf32(x - __uint_as_float(h));
}

// ---------------------------------------------------------------------------
// Projection GEMM via mma.sync tf32 + 3xTF32 compensation. (unchanged, passing)
// ---------------------------------------------------------------------------
#define A_STRIDE 36
#define B_STRIDE 136
#define A_STAGE_B 18432
#define B_STAGE_B 17408
#define B_BASE_B  (2 * A_STAGE_B)
#define PROJ_SMEM (2 * A_STAGE_B + 2 * B_STAGE_B)
#define PROJ_NT   (DIM / 32)

__global__ __launch_bounds__(256, 1)
void proj_mma_kernel(const float* __restrict__ X,
                     const float* __restrict__ Wq,
                     const float* __restrict__ Wk,
                     const float* __restrict__ Wv)
{
    extern __shared__ float smf[];
    const uint32_t sbase = smem_u32(smf);
    const int tid  = threadIdx.x;
    const int wid  = tid >> 5;
    const int lane = tid & 31;
    const int g    = lane >> 2;
    const int tg   = lane & 3;
    const int wm   = wid >> 1;
    const int wn   = wid & 1;
    const int z    = blockIdx.y;
    const int m0   = blockIdx.x * 128;

    const float* __restrict__ W = (z == 0) ? Wq : ((z == 1) ? Wk : Wv);
    float* __restrict__ C       = (z == 0) ? g_q : ((z == 1) ? g_k : g_v);

    float acc[2][8][4];
#pragma unroll
    for (int mf = 0; mf < 2; mf++)
#pragma unroll
        for (int nf = 0; nf < 8; nf++)
#pragma unroll
            for (int r = 0; r < 4; r++) acc[mf][nf][r] = 0.f;

    auto stage = [&](int s, int t) {
        const int k0 = t * 32;
#pragma unroll
        for (int q = 0; q < 4; q++) {
            int c   = q * 256 + tid;
            int row = c >> 3;
            int ch  = c & 7;
            cp16(sbase + s * A_STAGE_B + row * (A_STRIDE * 4) + ch * 16,
                 &X[(size_t)(m0 + row) * DIM + k0 + ch * 4]);
        }
#pragma unroll
        for (int q = 0; q < 4; q++) {
            int c   = q * 256 + tid;
            int row = c >> 5;
            int ch  = c & 31;
            cp16(sbase + B_BASE_B + s * B_STAGE_B + row * (B_STRIDE * 4) + ch * 16,
                 &W[(size_t)(k0 + row) * HD + ch * 4]);
        }
        CP_COMMIT();
    };

    stage(0, 0);

    for (int t = 0; t < PROJ_NT; t++) {
        const int s = t & 1;
        if (t + 1 < PROJ_NT) {
            stage(s ^ 1, t + 1);
            cp_wait<1>();
        } else {
            cp_wait<0>();
        }
        __syncthreads();

        const float* As = smf + s * (A_STAGE_B / 4);
        const float* Bs = smf + (B_BASE_B / 4) + s * (B_STAGE_B / 4);

#pragma unroll
        for (int sub = 0; sub < 4; sub++) {
            const int k8 = sub * 8;
            uint32_t ah[2][4], al[2][4];
#pragma unroll
            for (int mf = 0; mf < 2; mf++) {
                const int r = wm * 32 + mf * 16 + g;
                split2(As[r * A_STRIDE + k8 + tg],           ah[mf][0], al[mf][0]);
                split2(As[(r + 8) * A_STRIDE + k8 + tg],     ah[mf][1], al[mf][1]);
                split2(As[r * A_STRIDE + k8 + tg + 4],       ah[mf][2], al[mf][2]);
                split2(As[(r + 8) * A_STRIDE + k8 + tg + 4], ah[mf][3], al[mf][3]);
            }
            uint32_t bh[8][2], bl[8][2];
#pragma unroll
            for (int nf = 0; nf < 8; nf++) {
                const int n = wn * 64 + nf * 8 + g;
                split2(Bs[(k8 + tg) * B_STRIDE + n],     bh[nf][0], bl[nf][0]);
                split2(Bs[(k8 + tg + 4) * B_STRIDE + n], bh[nf][1], bl[nf][1]);
            }
#pragma unroll
            for (int mf = 0; mf < 2; mf++)
#pragma unroll
                for (int nf = 0; nf < 8; nf++) {
                    mma_tf32(acc[mf][nf], ah[mf], bh[nf]);
                    mma_tf32(acc[mf][nf], al[mf], bh[nf]);
                    mma_tf32(acc[mf][nf], ah[mf], bl[nf]);
                }
        }
        __syncthreads();
    }

#pragma unroll
    for (int mf = 0; mf < 2; mf++) {
        const int row = m0 + wm * 32 + mf * 16 + g;
#pragma unroll
        for (int nf = 0; nf < 8; nf++) {
            const int col = wn * 64 + nf * 8 + tg * 2;
            *(float2*)&C[(size_t)row * HD + col]       = make_float2(acc[mf][nf][0], acc[mf][nf][1]);
            *(float2*)&C[(size_t)(row + 8) * HD + col] = make_float2(acc[mf][nf][2], acc[mf][nf][3]);
        }
    }
}

// ---------------------------------------------------------------------------
// Flash attention (causal) on mma.sync tf32 3x.
// BQ=128 q-rows per CTA, BK=64 kv per tile. 8 warps; warp w owns q-rows
// [w*16, w*16+16) — softmax rows never cross warps.
// Smem (floats): Qs[128][132] | Ks[64][132] | Vs[64][132] | Ps[128][68]
// Fragment LDS conflict-free: bank = (4*row + k) & 31 for strides 132/68.
// ---------------------------------------------------------------------------
#define ATT_BQ 128
#define ATT_BK 64
#define QSTR 132
#define PSTR 68
#define QS_OFF 0
#define KS_OFF (ATT_BQ * QSTR)                  // 16896
#define VS_OFF (KS_OFF + ATT_BK * QSTR)         // 25344
#define PS_OFF (VS_OFF + ATT_BK * QSTR)         // 33792
#define ATT_SMEM ((PS_OFF + ATT_BQ * PSTR) * 4) // 169984 B

__global__ __launch_bounds__(256, 1)
void attn_mma_kernel(float* __restrict__ out)
{
    extern __shared__ float sm[];
    float* Qs = sm + QS_OFF;
    float* Ks = sm + KS_OFF;
    float* Vs = sm + VS_OFF;
    float* Ps = sm + PS_OFF;

    const int qt   = gridDim.x - 1 - blockIdx.x;   // heavy tiles first
    const int b    = blockIdx.y;
    const int tid  = threadIdx.x;
    const int wid  = tid >> 5;
    const int lane = tid & 31;
    const int g    = lane >> 2;       // 0..7
    const int tg   = lane & 3;        // 0..3
    const int wbase = wid * 16;       // warp's q-row base within tile
    const float scale = 0.08838834764831845f;      // 1/sqrt(128)

    // ---- load Q tile (scaled) ----
    const float* __restrict__ Qg = g_q + ((size_t)b * SEQ + (size_t)qt * ATT_BQ) * HD;
#pragma unroll
    for (int t = 0; t < 16; t++) {
        int idx = t * 256 + tid;      // float4 idx over 128x128
        int row = idx >> 5;
        int c4  = (idx & 31) * 4;
        float4 v = *(const float4*)&Qg[(size_t)row * HD + c4];
        v.x *= scale; v.y *= scale; v.z *= scale; v.w *= scale;
        *(float4*)&Qs[row * QSTR + c4] = v;
    }

    float m_i[2] = {-1e30f, -1e30f};
    float l_i[2] = {0.f, 0.f};
    float o[16][4];
#pragma unroll
    for (int nf = 0; nf < 16; nf++)
#pragma unroll
        for (int r = 0; r < 4; r++) o[nf][r] = 0.f;

    const int ntiles = 2 * qt + 2;
    const int rowg   = qt * ATT_BQ + wbase + g;    // global row of this thread's row 0

    for (int j = 0; j < ntiles; j++) {
        const float* __restrict__ Kg = g_k + ((size_t)b * SEQ + (size_t)j * ATT_BK) * HD;
        const float* __restrict__ Vg = g_v + ((size_t)b * SEQ + (size_t)j * ATT_BK) * HD;

        __syncthreads();   // all warps done reading previous Ks/Vs
#pragma unroll
        for (int t = 0; t < 8; t++) {
            int idx = t * 256 + tid;  // float4 idx over 64x128
            int row = idx >> 5;
            int c4  = (idx & 31) * 4;
            *(float4*)&Ks[row * QSTR + c4] = *(const float4*)&Kg[(size_t)row * HD + c4];
            *(float4*)&Vs[row * QSTR + c4] = *(const float4*)&Vg[(size_t)row * HD + c4];
        }
        __syncthreads();

        // ---- S = Q . K^T  (warp: 16 x 64), 3xTF32 ----
        float s[8][4];
#pragma unroll
        for (int nf = 0; nf < 8; nf++)
#pragma unroll
            for (int r = 0; r < 4; r++) s[nf][r] = 0.f;

#pragma unroll
        for (int k8 = 0; k8 < 16; k8++) {
            const int k = k8 * 8;
            uint32_t ah[4], al[4];
            split2(Qs[(wbase + g) * QSTR + k + tg],         ah[0], al[0]);
            split2(Qs[(wbase + g + 8) * QSTR + k + tg],     ah[1], al[1]);
            split2(Qs[(wbase + g) * QSTR + k + tg + 4],     ah[2], al[2]);
            split2(Qs[(wbase + g + 8) * QSTR + k + tg + 4], ah[3], al[3]);
#pragma unroll
            for (int nf = 0; nf < 8; nf++) {
                uint32_t bh[2], bl[2];
                split2(Ks[(nf * 8 + g) * QSTR + k + tg],     bh[0], bl[0]);
                split2(Ks[(nf * 8 + g) * QSTR + k + tg + 4], bh[1], bl[1]);
                mma_tf32(s[nf], ah, bh);
                mma_tf32(s[nf], al, bh);
                mma_tf32(s[nf], ah, bl);
            }
        }

        // ---- causal mask (only last two tiles can be partial) ----
        if (j >= 2 * qt) {
            const int colbase = j * ATT_BK;
#pragma unroll
            for (int nf = 0; nf < 8; nf++) {
                int c0 = colbase + nf * 8 + tg * 2;
                if (c0 > rowg)          s[nf][0] = -1e30f;
                if (c0 + 1 > rowg)      s[nf][1] = -1e30f;
                if (c0 > rowg + 8)      s[nf][2] = -1e30f;
                if (c0 + 1 > rowg + 8)  s[nf][3] = -1e30f;
            }
        }

        // ---- online softmax (rows g and g+8, quad reductions) ----
        float mx0 = -1e30f, mx1 = -1e30f;
#pragma unroll
        for (int nf = 0; nf < 8; nf++) {
            mx0 = fmaxf(mx0, fmaxf(s[nf][0], s[nf][1]));
            mx1 = fmaxf(mx1, fmaxf(s[nf][2], s[nf][3]));
        }
        mx0 = fmaxf(mx0, __shfl_xor_sync(0xffffffffu, mx0, 1));
        mx0 = fmaxf(mx0, __shfl_xor_sync(0xffffffffu, mx0, 2));
        mx1 = fmaxf(mx1, __shfl_xor_sync(0xffffffffu, mx1, 1));
        mx1 = fmaxf(mx1, __shfl_xor_sync(0xffffffffu, mx1, 2));

        float mn0 = fmaxf(m_i[0], mx0);
        float mn1 = fmaxf(m_i[1], mx1);
        float al0 = __expf(m_i[0] - mn0);
        float al1 = __expf(m_i[1] - mn1);

        float rs0 = 0.f, rs1 = 0.f;
#pragma unroll
        for (int nf = 0; nf < 8; nf++) {
            s[nf][0] = __expf(s[nf][0] - mn0);
            s[nf][1] = __expf(s[nf][1] - mn0);
            s[nf][2] = __expf(s[nf][2] - mn1);
            s[nf][3] = __expf(s[nf][3] - mn1);
            rs0 += s[nf][0] + s[nf][1];
            rs1 += s[nf][2] + s[nf][3];
        }
        rs0 += __shfl_xor_sync(0xffffffffu, rs0, 1);
        rs0 += __shfl_xor_sync(0xffffffffu, rs0, 2);
        rs1 += __shfl_xor_sync(0xffffffffu, rs1, 1);
        rs1 += __shfl_xor_sync(0xffffffffu, rs1, 2);

        l_i[0] = l_i[0] * al0 + rs0;
        l_i[1] = l_i[1] * al1 + rs1;
        m_i[0] = mn0;
        m_i[1] = mn1;

#pragma unroll
        for (int nf = 0; nf < 16; nf++) {
            o[nf][0] *= al0; o[nf][1] *= al0;
            o[nf][2] *= al1; o[nf][3] *= al1;
        }

        // ---- stage P to warp-private smem rows ----
#pragma unroll
        for (int nf = 0; nf < 8; nf++) {
            *(float2*)&Ps[(wbase + g) * PSTR + nf * 8 + tg * 2]     = make_float2(s[nf][0], s[nf][1]);
            *(float2*)&Ps[(wbase + g + 8) * PSTR + nf * 8 + tg * 2] = make_float2(s[nf][2], s[nf][3]);
        }
        __syncwarp();

        // ---- O += P . V  (warp: 16 x 128), 3xTF32 ----
#pragma unroll
        for (int k8 = 0; k8 < 8; k8++) {
            const int k = k8 * 8;
            uint32_t ph[4], pl[4];
            split2(Ps[(wbase + g) * PSTR + k + tg],         ph[0], pl[0]);
            split2(Ps[(wbase + g + 8) * PSTR + k + tg],     ph[1], pl[1]);
            split2(Ps[(wbase + g) * PSTR + k + tg + 4],     ph[2], pl[2]);
            split2(Ps[(wbase + g + 8) * PSTR + k + tg + 4], ph[3], pl[3]);
#pragma unroll
            for (int nf = 0; nf < 16; nf++) {
                uint32_t vh[2], vl[2];
                split2(Vs[(k + tg) * QSTR + nf * 8 + g],     vh[0], vl[0]);
                split2(Vs[(k + tg + 4) * QSTR + nf * 8 + g], vh[1], vl[1]);
                mma_tf32(o[nf], ph, vh);
                mma_tf32(o[nf], pl, vh);
                mma_tf32(o[nf], ph, vl);
            }
        }
        __syncwarp();   // P reads done before next iteration overwrites
    }

    // ---- normalize and store ----
    const float inv0 = 1.f / l_i[0];
    const float inv1 = 1.f / l_i[1];
    const size_t row0 = (size_t)b * SEQ + (size_t)qt * ATT_BQ + wbase + g;
#pragma unroll
    for (int nf = 0; nf < 16; nf++) {
        const int col = nf * 8 + tg * 2;
        *(float2*)&out[row0 * HD + col]       = make_float2(o[nf][0] * inv0, o[nf][1] * inv0);
        *(float2*)&out[(row0 + 8) * HD + col] = make_float2(o[nf][2] * inv1, o[nf][3] * inv1);
    }
}

// ---------------------------------------------------------------------------
extern "C" void kernel_launch(void* const* d_in, const int* in_sizes, int n_in,
                              void* d_out, int out_size)
{
    const float* x  = (const float*)d_in[0];
    const float* wq = (const float*)d_in[1];
    const float* wk = (const float*)d_in[2];
    const float* wv = (const float*)d_in[3];
    float* out = (float*)d_out;

    cudaFuncSetAttribute(proj_mma_kernel,
                         cudaFuncAttributeMaxDynamicSharedMemorySize, PROJ_SMEM);
    cudaFuncSetAttribute(attn_mma_kernel,
                         cudaFuncAttributeMaxDynamicSharedMemorySize, ATT_SMEM);

    dim3 gridP((BSZ * SEQ) / 128, 3);
    proj_mma_kernel<<<gridP, 256, PROJ_SMEM>>>(x, wq, wk, wv);

    dim3 gridA(SEQ / ATT_BQ, BSZ);
    attn_mma_kernel<<<gridA, 256, ATT_SMEM>>>(out);
}

// round 6
// speedup vs baseline: 1.6682x; 1.2945x over previous
#include <cuda_runtime.h>
#include <math.h>
#include <cstdint>

#define BSZ 16
#define SEQ 2048
#define DIM 1024
#define HD  128

// Scratch for Q, K, V projections — __device__ globals per the no-allocation rule.
__device__ float g_q[BSZ * SEQ * HD];
__device__ float g_k[BSZ * SEQ * HD];
__device__ float g_v[BSZ * SEQ * HD];

// ---------------------------------------------------------------------------
// Helpers
// ---------------------------------------------------------------------------
__device__ __forceinline__ uint32_t smem_u32(const void* p) {
    uint32_t a;
    asm("{ .reg .u64 t; cvta.to.shared.u64 t, %1; cvt.u32.u64 %0, t; }" : "=r"(a) : "l"(p));
    return a;
}

__device__ __forceinline__ void cp16(uint32_t dst, const void* src) {
    asm volatile("cp.async.cg.shared.global [%0], [%1], 16;" :: "r"(dst), "l"(src));
}
#define CP_COMMIT() asm volatile("cp.async.commit_group;" ::: "memory")
template <int N>
__device__ __forceinline__ void cp_wait() {
    asm volatile("cp.async.wait_group %0;" :: "n"(N) : "memory");
}

__device__ __forceinline__ uint32_t f2tf32(float x) {
    uint32_t r;
    asm("cvt.rna.tf32.f32 %0, %1;" : "=r"(r) : "f"(x));
    return r;
}

// Cheap compensated split: HMMA truncates b32 operands to tf32 (top 19 bits),
// so pass the RAW float as "hi" and lo = x - (x & 0xFFFFE000). hi+lo == x exactly.
__device__ __forceinline__ float tf32_lo(float x) {
    return x - __uint_as_float(__float_as_uint(x) & 0xFFFFE000u);
}

__device__ __forceinline__ void mma_tf32(float* c, const uint32_t* a, const uint32_t* b) {
    asm volatile(
        "mma.sync.aligned.m16n8k8.row.col.f32.tf32.tf32.f32 "
        "{%0,%1,%2,%3}, {%4,%5,%6,%7}, {%8,%9}, {%0,%1,%2,%3};"
        : "+f"(c[0]), "+f"(c[1]), "+f"(c[2]), "+f"(c[3])
        : "r"(a[0]), "r"(a[1]), "r"(a[2]), "r"(a[3]), "r"(b[0]), "r"(b[1]));
}

// ---------------------------------------------------------------------------
// Projection GEMM via mma.sync tf32, compensated 3x (raw-hi + lo trick).
// C[32768,128] = X[32768,1024] * W[1024,128].  blockIdx.y = z in {q,k,v}.
// 2 CTAs/SM (70 KB smem), B fragments loaded per-nf to keep regs < 128.
// ---------------------------------------------------------------------------
#define A_STRIDE 36
#define B_STRIDE 136
#define A_STAGE_B 18432
#define B_STAGE_B 17408
#define B_BASE_B  (2 * A_STAGE_B)
#define PROJ_SMEM (2 * A_STAGE_B + 2 * B_STAGE_B)
#define PROJ_NT   (DIM / 32)

__global__ __launch_bounds__(256, 2)
void proj_mma_kernel(const float* __restrict__ X,
                     const float* __restrict__ Wq,
                     const float* __restrict__ Wk,
                     const float* __restrict__ Wv)
{
    extern __shared__ float smf[];
    const uint32_t sbase = smem_u32(smf);
    const int tid  = threadIdx.x;
    const int wid  = tid >> 5;
    const int lane = tid & 31;
    const int g    = lane >> 2;
    const int tg   = lane & 3;
    const int wm   = wid >> 1;
    const int wn   = wid & 1;
    const int z    = blockIdx.y;
    const int m0   = blockIdx.x * 128;

    const float* __restrict__ W = (z == 0) ? Wq : ((z == 1) ? Wk : Wv);
    float* __restrict__ C       = (z == 0) ? g_q : ((z == 1) ? g_k : g_v);

    float acc[2][8][4];
#pragma unroll
    for (int mf = 0; mf < 2; mf++)
#pragma unroll
        for (int nf = 0; nf < 8; nf++)
#pragma unroll
            for (int r = 0; r < 4; r++) acc[mf][nf][r] = 0.f;

    auto stage = [&](int s, int t) {
        const int k0 = t * 32;
#pragma unroll
        for (int q = 0; q < 4; q++) {
            int c   = q * 256 + tid;
            int row = c >> 3;
            int ch  = c & 7;
            cp16(sbase + s * A_STAGE_B + row * (A_STRIDE * 4) + ch * 16,
                 &X[(size_t)(m0 + row) * DIM + k0 + ch * 4]);
        }
#pragma unroll
        for (int q = 0; q < 4; q++) {
            int c   = q * 256 + tid;
            int row = c >> 5;
            int ch  = c & 31;
            cp16(sbase + B_BASE_B + s * B_STAGE_B + row * (B_STRIDE * 4) + ch * 16,
                 &W[(size_t)(k0 + row) * HD + ch * 4]);
        }
        CP_COMMIT();
    };

    stage(0, 0);

    for (int t = 0; t < PROJ_NT; t++) {
        const int s = t & 1;
        if (t + 1 < PROJ_NT) {
            stage(s ^ 1, t + 1);
            cp_wait<1>();
        } else {
            cp_wait<0>();
        }
        __syncthreads();

        const float* As = smf + s * (A_STAGE_B / 4);
        const float* Bs = smf + (B_BASE_B / 4) + s * (B_STAGE_B / 4);

#pragma unroll
        for (int sub = 0; sub < 4; sub++) {
            const int k8 = sub * 8;
            uint32_t ah[2][4], al[2][4];
#pragma unroll
            for (int mf = 0; mf < 2; mf++) {
                const int r = wm * 32 + mf * 16 + g;
                float a0 = As[r * A_STRIDE + k8 + tg];
                float a1 = As[(r + 8) * A_STRIDE + k8 + tg];
                float a2 = As[r * A_STRIDE + k8 + tg + 4];
                float a3 = As[(r + 8) * A_STRIDE + k8 + tg + 4];
                ah[mf][0] = __float_as_uint(a0); al[mf][0] = __float_as_uint(tf32_lo(a0));
                ah[mf][1] = __float_as_uint(a1); al[mf][1] = __float_as_uint(tf32_lo(a1));
                ah[mf][2] = __float_as_uint(a2); al[mf][2] = __float_as_uint(tf32_lo(a2));
                ah[mf][3] = __float_as_uint(a3); al[mf][3] = __float_as_uint(tf32_lo(a3));
            }
#pragma unroll
            for (int nf = 0; nf < 8; nf++) {
                const int n = wn * 64 + nf * 8 + g;
                float b0 = Bs[(k8 + tg) * B_STRIDE + n];
                float b1 = Bs[(k8 + tg + 4) * B_STRIDE + n];
                uint32_t bh[2] = {__float_as_uint(b0), __float_as_uint(b1)};
                uint32_t bl[2] = {__float_as_uint(tf32_lo(b0)), __float_as_uint(tf32_lo(b1))};
#pragma unroll
                for (int mf = 0; mf < 2; mf++) {
                    mma_tf32(acc[mf][nf], ah[mf], bh);
                    mma_tf32(acc[mf][nf], al[mf], bh);
                    mma_tf32(acc[mf][nf], ah[mf], bl);
                }
            }
        }
        __syncthreads();
    }

#pragma unroll
    for (int mf = 0; mf < 2; mf++) {
        const int row = m0 + wm * 32 + mf * 16 + g;
#pragma unroll
        for (int nf = 0; nf < 8; nf++) {
            const int col = wn * 64 + nf * 8 + tg * 2;
            *(float2*)&C[(size_t)row * HD + col]       = make_float2(acc[mf][nf][0], acc[mf][nf][1]);
            *(float2*)&C[(size_t)(row + 8) * HD + col] = make_float2(acc[mf][nf][2], acc[mf][nf][3]);
        }
    }
}

// ---------------------------------------------------------------------------
// Flash attention (causal), mma.sync tf32.
// 512 threads, 16 warps as 8M x 2N: warp (wm, wn) computes
//   QK^T: rows wm*16..+16, score cols wn*32..+32   (3x compensated)
//   PV:   rows wm*16..+16, out   cols wn*64..+64   (2x: P tf32-rounded, V hi/lo)
// Cross-warp softmax: pairwise (max,sum) merge via smem + named barrier (1+wm).
// Smem floats: Qs[128][132] Ks[64][132] Vs[64][136] Ps[128][68] Red[128][2]f2
// ---------------------------------------------------------------------------
#define ATT_BQ 128
#define ATT_BK 64
#define QSTR 132
#define KSTR 132
#define VSTR 136
#define PSTR 68
#define QS_OFF 0
#define KS_OFF (ATT_BQ * QSTR)                     // 16896
#define VS_OFF (KS_OFF + ATT_BK * KSTR)            // 25344
#define PS_OFF (VS_OFF + ATT_BK * VSTR)            // 34048
#define RED_OFF (PS_OFF + ATT_BQ * PSTR)           // 42752
#define ATT_SMEM ((RED_OFF + ATT_BQ * 2 * 2) * 4)  // 173056 B

__global__ __launch_bounds__(512, 1)
void attn_mma_kernel(float* __restrict__ out)
{
    extern __shared__ float sm[];
    float* Qs  = sm + QS_OFF;
    float* Ks  = sm + KS_OFF;
    float* Vs  = sm + VS_OFF;
    float* Ps  = sm + PS_OFF;
    float2* Red = (float2*)(sm + RED_OFF);

    const int qt   = gridDim.x - 1 - blockIdx.x;   // heavy tiles first
    const int b    = blockIdx.y;
    const int tid  = threadIdx.x;
    const int wid  = tid >> 5;
    const int lane = tid & 31;
    const int g    = lane >> 2;
    const int tg   = lane & 3;
    const int wm   = wid >> 1;        // 0..7
    const int wn   = wid & 1;         // 0..1
    const int r0   = wm * 16 + g;     // warp row 0 (tile-local)
    const float scale = 0.08838834764831845f;      // 1/sqrt(128)

    // ---- load Q tile (scaled) ----
    const float* __restrict__ Qg = g_q + ((size_t)b * SEQ + (size_t)qt * ATT_BQ) * HD;
#pragma unroll
    for (int t = 0; t < 8; t++) {
        int idx = t * 512 + tid;      // float4 idx over 128x128
        int row = idx >> 5;
        int c4  = (idx & 31) * 4;
        float4 v = *(const float4*)&Qg[(size_t)row * HD + c4];
        v.x *= scale; v.y *= scale; v.z *= scale; v.w *= scale;
        *(float4*)&Qs[row * QSTR + c4] = v;
    }

    float m_i[2] = {-1e30f, -1e30f};
    float l_i[2] = {0.f, 0.f};
    float o[8][4];
#pragma unroll
    for (int nf = 0; nf < 8; nf++)
#pragma unroll
        for (int r = 0; r < 4; r++) o[nf][r] = 0.f;

    const int ntiles = 2 * qt + 2;
    const int rowg   = qt * ATT_BQ + r0;

    for (int j = 0; j < ntiles; j++) {
        const float* __restrict__ Kg = g_k + ((size_t)b * SEQ + (size_t)j * ATT_BK) * HD;
        const float* __restrict__ Vg = g_v + ((size_t)b * SEQ + (size_t)j * ATT_BK) * HD;

        __syncthreads();   // all warps done reading previous Ks/Vs/Ps
#pragma unroll
        for (int t = 0; t < 4; t++) {
            int idx = t * 512 + tid;  // float4 idx over 64x128
            int row = idx >> 5;
            int c4  = (idx & 31) * 4;
            *(float4*)&Ks[row * KSTR + c4] = *(const float4*)&Kg[(size_t)row * HD + c4];
            *(float4*)&Vs[row * VSTR + c4] = *(const float4*)&Vg[(size_t)row * HD + c4];
        }
        __syncthreads();

        // ---- S = Q . K^T  (warp: 16 rows x 32 cols), compensated 3x ----
        float s[4][4];
#pragma unroll
        for (int nf = 0; nf < 4; nf++)
#pragma unroll
            for (int r = 0; r < 4; r++) s[nf][r] = 0.f;

#pragma unroll
        for (int k8 = 0; k8 < 16; k8++) {
            const int k = k8 * 8;
            float a0 = Qs[r0 * QSTR + k + tg];
            float a1 = Qs[(r0 + 8) * QSTR + k + tg];
            float a2 = Qs[r0 * QSTR + k + tg + 4];
            float a3 = Qs[(r0 + 8) * QSTR + k + tg + 4];
            uint32_t ah[4] = {__float_as_uint(a0), __float_as_uint(a1),
                              __float_as_uint(a2), __float_as_uint(a3)};
            uint32_t al[4] = {__float_as_uint(tf32_lo(a0)), __float_as_uint(tf32_lo(a1)),
                              __float_as_uint(tf32_lo(a2)), __float_as_uint(tf32_lo(a3))};
#pragma unroll
            for (int nf = 0; nf < 4; nf++) {
                const int kr = (wn * 32 + nf * 8 + g) * KSTR + k;
                float b0 = Ks[kr + tg];
                float b1 = Ks[kr + tg + 4];
                uint32_t bh[2] = {__float_as_uint(b0), __float_as_uint(b1)};
                uint32_t bl[2] = {__float_as_uint(tf32_lo(b0)), __float_as_uint(tf32_lo(b1))};
                mma_tf32(s[nf], ah, bh);
                mma_tf32(s[nf], al, bh);
                mma_tf32(s[nf], ah, bl);
            }
        }

        // ---- causal mask (only last two kv tiles can intersect the diagonal) ----
        if (j >= 2 * qt) {
            const int colbase = j * ATT_BK + wn * 32;
#pragma unroll
            for (int nf = 0; nf < 4; nf++) {
                int c0 = colbase + nf * 8 + tg * 2;
                if (c0 > rowg)          s[nf][0] = -1e30f;
                if (c0 + 1 > rowg)      s[nf][1] = -1e30f;
                if (c0 > rowg + 8)      s[nf][2] = -1e30f;
                if (c0 + 1 > rowg + 8)  s[nf][3] = -1e30f;
            }
        }

        // ---- local (32-col) row max ----
        float mx0 = -1e30f, mx1 = -1e30f;
#pragma unroll
        for (int nf = 0; nf < 4; nf++) {
            mx0 = fmaxf(mx0, fmaxf(s[nf][0], s[nf][1]));
            mx1 = fmaxf(mx1, fmaxf(s[nf][2], s[nf][3]));
        }
        mx0 = fmaxf(mx0, __shfl_xor_sync(0xffffffffu, mx0, 1));
        mx0 = fmaxf(mx0, __shfl_xor_sync(0xffffffffu, mx0, 2));
        mx1 = fmaxf(mx1, __shfl_xor_sync(0xffffffffu, mx1, 1));
        mx1 = fmaxf(mx1, __shfl_xor_sync(0xffffffffu, mx1, 2));

        // ---- exp relative to local max + local sums ----
        float rs0 = 0.f, rs1 = 0.f;
#pragma unroll
        for (int nf = 0; nf < 4; nf++) {
            s[nf][0] = __expf(s[nf][0] - mx0);
            s[nf][1] = __expf(s[nf][1] - mx0);
            s[nf][2] = __expf(s[nf][2] - mx1);
            s[nf][3] = __expf(s[nf][3] - mx1);
            rs0 += s[nf][0] + s[nf][1];
            rs1 += s[nf][2] + s[nf][3];
        }
        rs0 += __shfl_xor_sync(0xffffffffu, rs0, 1);
        rs0 += __shfl_xor_sync(0xffffffffu, rs0, 2);
        rs1 += __shfl_xor_sync(0xffffffffu, rs1, 1);
        rs1 += __shfl_xor_sync(0xffffffffu, rs1, 2);

        // ---- pairwise merge with the other N-warp ----
        if (tg == 0) {
            Red[r0 * 2 + wn]       = make_float2(mx0, rs0);
            Red[(r0 + 8) * 2 + wn] = make_float2(mx1, rs1);
        }
        asm volatile("bar.sync %0, 64;" :: "r"(1 + wm) : "memory");
        float2 p0 = Red[r0 * 2 + (wn ^ 1)];
        float2 p1 = Red[(r0 + 8) * 2 + (wn ^ 1)];

        float mn0 = fmaxf(m_i[0], fmaxf(mx0, p0.x));
        float mn1 = fmaxf(m_i[1], fmaxf(mx1, p1.x));
        float f0  = __expf(mx0 - mn0);
        float f1  = __expf(mx1 - mn1);
        float al0 = __expf(m_i[0] - mn0);
        float al1 = __expf(m_i[1] - mn1);
        l_i[0] = l_i[0] * al0 + rs0 * f0 + p0.y * __expf(p0.x - mn0);
        l_i[1] = l_i[1] * al1 + rs1 * f1 + p1.y * __expf(p1.x - mn1);
        m_i[0] = mn0;
        m_i[1] = mn1;

#pragma unroll
        for (int nf = 0; nf < 8; nf++) {
            o[nf][0] *= al0; o[nf][1] *= al0;
            o[nf][2] *= al1; o[nf][3] *= al1;
        }

        // ---- stage P (rescaled to global max, RNA-rounded to tf32) ----
#pragma unroll
        for (int nf = 0; nf < 4; nf++) {
            float2 w0 = make_float2(__uint_as_float(f2tf32(s[nf][0] * f0)),
                                    __uint_as_float(f2tf32(s[nf][1] * f0)));
            float2 w1 = make_float2(__uint_as_float(f2tf32(s[nf][2] * f1)),
                                    __uint_as_float(f2tf32(s[nf][3] * f1)));
            *(float2*)&Ps[r0 * PSTR + wn * 32 + nf * 8 + tg * 2]       = w0;
            *(float2*)&Ps[(r0 + 8) * PSTR + wn * 32 + nf * 8 + tg * 2] = w1;
        }
        asm volatile("bar.sync %0, 64;" :: "r"(1 + wm) : "memory");

        // ---- O += P . V  (warp: 16 rows x 64 out-cols), compensated 2x ----
#pragma unroll
        for (int k8 = 0; k8 < 8; k8++) {
            const int k = k8 * 8;
            uint32_t ph[4] = {
                __float_as_uint(Ps[r0 * PSTR + k + tg]),
                __float_as_uint(Ps[(r0 + 8) * PSTR + k + tg]),
                __float_as_uint(Ps[r0 * PSTR + k + tg + 4]),
                __float_as_uint(Ps[(r0 + 8) * PSTR + k + tg + 4])};
#pragma unroll
            for (int nf = 0; nf < 8; nf++) {
                const int col = wn * 64 + nf * 8 + g;
                float v0 = Vs[(k + tg) * VSTR + col];
                float v1 = Vs[(k + tg + 4) * VSTR + col];
                uint32_t vh[2] = {__float_as_uint(v0), __float_as_uint(v1)};
                uint32_t vl[2] = {__float_as_uint(tf32_lo(v0)), __float_as_uint(tf32_lo(v1))};
                mma_tf32(o[nf], ph, vh);
                mma_tf32(o[nf], ph, vl);
            }
        }
    }

    // ---- normalize and store ----
    const float inv0 = 1.f / l_i[0];
    const float inv1 = 1.f / l_i[1];
    const size_t orow = (size_t)b * SEQ + (size_t)qt * ATT_BQ + r0;
#pragma unroll
    for (int nf = 0; nf < 8; nf++) {
        const int col = wn * 64 + nf * 8 + tg * 2;
        *(float2*)&out[orow * HD + col]       = make_float2(o[nf][0] * inv0, o[nf][1] * inv0);
        *(float2*)&out[(orow + 8) * HD + col] = make_float2(o[nf][2] * inv1, o[nf][3] * inv1);
    }
}

// ---------------------------------------------------------------------------
extern "C" void kernel_launch(void* const* d_in, const int* in_sizes, int n_in,
                              void* d_out, int out_size)
{
    const float* x  = (const float*)d_in[0];
    const float* wq = (const float*)d_in[1];
    const float* wk = (const float*)d_in[2];
    const float* wv = (const float*)d_in[3];
    float* out = (float*)d_out;

    cudaFuncSetAttribute(proj_mma_kernel,
                         cudaFuncAttributeMaxDynamicSharedMemorySize, PROJ_SMEM);
    cudaFuncSetAttribute(attn_mma_kernel,
                         cudaFuncAttributeMaxDynamicSharedMemorySize, ATT_SMEM);

    dim3 gridP((BSZ * SEQ) / 128, 3);
    proj_mma_kernel<<<gridP, 256, PROJ_SMEM>>>(x, wq, wk, wv);

    dim3 gridA(SEQ / ATT_BQ, BSZ);
    attn_mma_kernel<<<gridA, 512, ATT_SMEM>>>(out);
}

// round 8
// speedup vs baseline: 2.0786x; 1.2460x over previous
#include <cuda_runtime.h>
#include <math.h>
#include <cstdint>

#define BSZ 16
#define SEQ 2048
#define DIM 1024
#define HD  128

// Scratch for Q, K, V projections — __device__ globals per the no-allocation rule.
__device__ float g_q[BSZ * SEQ * HD];
__device__ float g_k[BSZ * SEQ * HD];
__device__ float g_v[BSZ * SEQ * HD];

// ---------------------------------------------------------------------------
// Helpers
// ---------------------------------------------------------------------------
__device__ __forceinline__ uint32_t smem_u32(const void* p) {
    uint32_t a;
    asm("{ .reg .u64 t; cvta.to.shared.u64 t, %1; cvt.u32.u64 %0, t; }" : "=r"(a) : "l"(p));
    return a;
}

__device__ __forceinline__ void cp16(uint32_t dst, const void* src) {
    asm volatile("cp.async.cg.shared.global [%0], [%1], 16;" :: "r"(dst), "l"(src));
}
#define CP_COMMIT() asm volatile("cp.async.commit_group;" ::: "memory")
template <int N>
__device__ __forceinline__ void cp_wait() {
    asm volatile("cp.async.wait_group %0;" :: "n"(N) : "memory");
}

// RNA round to tf32 (unbiased; keeps value as fp32 with low 13 bits zero)
__device__ __forceinline__ uint32_t f2tf32(float x) {
    uint32_t r;
    asm("cvt.rna.tf32.f32 %0, %1;" : "=r"(r) : "f"(x));
    return r;
}
__device__ __forceinline__ float rna_tf32(float x) {
    return __uint_as_float(f2tf32(x));
}

// HMMA truncates b32 operands to tf32 (top 19 bits). lo = x - trunc(x), so
// passing (raw x, lo) as two operands reproduces x exactly.
__device__ __forceinline__ float tf32_lo(float x) {
    return x - __uint_as_float(__float_as_uint(x) & 0xFFFFE000u);
}

__device__ __forceinline__ void mma_tf32(float* c, const uint32_t* a, const uint32_t* b) {
    asm volatile(
        "mma.sync.aligned.m16n8k8.row.col.f32.tf32.tf32.f32 "
        "{%0,%1,%2,%3}, {%4,%5,%6,%7}, {%8,%9}, {%0,%1,%2,%3};"
        : "+f"(c[0]), "+f"(c[1]), "+f"(c[2]), "+f"(c[3])
        : "r"(a[0]), "r"(a[1]), "r"(a[2]), "r"(a[3]), "r"(b[0]), "r"(b[1]));
}

// ---------------------------------------------------------------------------
// Projection GEMM via mma.sync tf32, exact-A 2x:
//   C = (A_raw + A_lo) . rna(B)   — B rounded (unbiased), A exact.
// C[32768,128] = X[32768,1024] * W[1024,128].  blockIdx.y = z in {q,k,v}.
// ---------------------------------------------------------------------------
#define A_STRIDE 36
#define B_STRIDE 136
#define A_STAGE_B 18432
#define B_STAGE_B 17408
#define B_BASE_B  (2 * A_STAGE_B)
#define PROJ_SMEM (2 * A_STAGE_B + 2 * B_STAGE_B)
#define PROJ_NT   (DIM / 32)

__global__ __launch_bounds__(256, 2)
void proj_mma_kernel(const float* __restrict__ X,
                     const float* __restrict__ Wq,
                     const float* __restrict__ Wk,
                     const float* __restrict__ Wv)
{
    extern __shared__ float smf[];
    const uint32_t sbase = smem_u32(smf);
    const int tid  = threadIdx.x;
    const int wid  = tid >> 5;
    const int lane = tid & 31;
    const int g    = lane >> 2;
    const int tg   = lane & 3;
    const int wm   = wid >> 1;
    const int wn   = wid & 1;
    const int z    = blockIdx.y;
    const int m0   = blockIdx.x * 128;

    const float* __restrict__ W = (z == 0) ? Wq : ((z == 1) ? Wk : Wv);
    float* __restrict__ C       = (z == 0) ? g_q : ((z == 1) ? g_k : g_v);

    float acc[2][8][4];
#pragma unroll
    for (int mf = 0; mf < 2; mf++)
#pragma unroll
        for (int nf = 0; nf < 8; nf++)
#pragma unroll
            for (int r = 0; r < 4; r++) acc[mf][nf][r] = 0.f;

    auto stage = [&](int s, int t) {
        const int k0 = t * 32;
#pragma unroll
        for (int q = 0; q < 4; q++) {
            int c   = q * 256 + tid;
            int row = c >> 3;
            int ch  = c & 7;
            cp16(sbase + s * A_STAGE_B + row * (A_STRIDE * 4) + ch * 16,
                 &X[(size_t)(m0 + row) * DIM + k0 + ch * 4]);
        }
#pragma unroll
        for (int q = 0; q < 4; q++) {
            int c   = q * 256 + tid;
            int row = c >> 5;
            int ch  = c & 31;
            cp16(sbase + B_BASE_B + s * B_STAGE_B + row * (B_STRIDE * 4) + ch * 16,
                 &W[(size_t)(k0 + row) * HD + ch * 4]);
        }
        CP_COMMIT();
    };

    stage(0, 0);

    for (int t = 0; t < PROJ_NT; t++) {
        const int s = t & 1;
        if (t + 1 < PROJ_NT) {
            stage(s ^ 1, t + 1);
            cp_wait<1>();
        } else {
            cp_wait<0>();
        }
        __syncthreads();

        const float* As = smf + s * (A_STAGE_B / 4);
        const float* Bs = smf + (B_BASE_B / 4) + s * (B_STAGE_B / 4);

#pragma unroll
        for (int sub = 0; sub < 4; sub++) {
            const int k8 = sub * 8;
            uint32_t ah[2][4], al[2][4];
#pragma unroll
            for (int mf = 0; mf < 2; mf++) {
                const int r = wm * 32 + mf * 16 + g;
                float a0 = As[r * A_STRIDE + k8 + tg];
                float a1 = As[(r + 8) * A_STRIDE + k8 + tg];
                float a2 = As[r * A_STRIDE + k8 + tg + 4];
                float a3 = As[(r + 8) * A_STRIDE + k8 + tg + 4];
                ah[mf][0] = __float_as_uint(a0); al[mf][0] = __float_as_uint(tf32_lo(a0));
                ah[mf][1] = __float_as_uint(a1); al[mf][1] = __float_as_uint(tf32_lo(a1));
                ah[mf][2] = __float_as_uint(a2); al[mf][2] = __float_as_uint(tf32_lo(a2));
                ah[mf][3] = __float_as_uint(a3); al[mf][3] = __float_as_uint(tf32_lo(a3));
            }
#pragma unroll
            for (int nf = 0; nf < 8; nf++) {
                const int n = wn * 64 + nf * 8 + g;
                // RNA-round B (unbiased) — replaces biased HW truncation.
                uint32_t bh[2] = {f2tf32(Bs[(k8 + tg) * B_STRIDE + n]),
                                  f2tf32(Bs[(k8 + tg + 4) * B_STRIDE + n])};
#pragma unroll
                for (int mf = 0; mf < 2; mf++) {
                    mma_tf32(acc[mf][nf], ah[mf], bh);
                    mma_tf32(acc[mf][nf], al[mf], bh);
                }
            }
        }
        __syncthreads();
    }

#pragma unroll
    for (int mf = 0; mf < 2; mf++) {
        const int row = m0 + wm * 32 + mf * 16 + g;
#pragma unroll
        for (int nf = 0; nf < 8; nf++) {
            const int col = wn * 64 + nf * 8 + tg * 2;
            *(float2*)&C[(size_t)row * HD + col]       = make_float2(acc[mf][nf][0], acc[mf][nf][1]);
            *(float2*)&C[(size_t)(row + 8) * HD + col] = make_float2(acc[mf][nf][2], acc[mf][nf][3]);
        }
    }
}

// ---------------------------------------------------------------------------
// Flash attention (causal), mma.sync tf32.
// 512 threads, warps as 8M x 2N.
// QK^T: exact-Q 2x — Q (raw hi + lo), K RNA-rounded ONCE at smem fill.
// PV:   exact-V 2x — P RNA-rounded once; V pre-split to VH raw / VL lo.
// Smem floats: Qs[128][132] Ks[64][132] Vh[64][136] Vl[64][136] Ps[128][68] Red
// ---------------------------------------------------------------------------
#define ATT_BQ 128
#define ATT_BK 64
#define QSTR 132
#define KSTR 132
#define VSTR 136
#define PSTR 68
#define QS_OFF 0
#define KS_OFF (ATT_BQ * QSTR)                     // 16896
#define VH_OFF (KS_OFF + ATT_BK * KSTR)            // 25344
#define VL_OFF (VH_OFF + ATT_BK * VSTR)            // 34048
#define PS_OFF (VL_OFF + ATT_BK * VSTR)            // 42752
#define RED_OFF (PS_OFF + ATT_BQ * PSTR)           // 51456
#define ATT_SMEM ((RED_OFF + ATT_BQ * 2 * 2) * 4)  // 207872 B

__global__ __launch_bounds__(512, 1)
void attn_mma_kernel(float* __restrict__ out)
{
    extern __shared__ float sm[];
    float* Qs  = sm + QS_OFF;
    float* Ks  = sm + KS_OFF;
    float* Vh  = sm + VH_OFF;
    float* Vl  = sm + VL_OFF;
    float* Ps  = sm + PS_OFF;
    float2* Red = (float2*)(sm + RED_OFF);

    const int qt   = gridDim.x - 1 - blockIdx.x;   // heavy tiles first
    const int b    = blockIdx.y;
    const int tid  = threadIdx.x;
    const int lane = tid & 31;
    const int wid  = tid >> 5;
    const int g    = lane >> 2;
    const int tg   = lane & 3;
    const int wm   = wid >> 1;        // 0..7
    const int wn   = wid & 1;         // 0..1
    const int r0   = wm * 16 + g;     // warp row 0 (tile-local)
    const float scale = 0.08838834764831845f;      // 1/sqrt(128)

    // ---- load Q tile (scaled) ----
    const float* __restrict__ Qg = g_q + ((size_t)b * SEQ + (size_t)qt * ATT_BQ) * HD;
#pragma unroll
    for (int t = 0; t < 8; t++) {
        int idx = t * 512 + tid;      // float4 idx over 128x128
        int row = idx >> 5;
        int c4  = (idx & 31) * 4;
        float4 v = *(const float4*)&Qg[(size_t)row * HD + c4];
        v.x *= scale; v.y *= scale; v.z *= scale; v.w *= scale;
        *(float4*)&Qs[row * QSTR + c4] = v;
    }

    float m_i[2] = {-1e30f, -1e30f};
    float l_i[2] = {0.f, 0.f};
    float o[8][4];
#pragma unroll
    for (int nf = 0; nf < 8; nf++)
#pragma unroll
        for (int r = 0; r < 4; r++) o[nf][r] = 0.f;

    const int ntiles = 2 * qt + 2;
    const int rowg   = qt * ATT_BQ + r0;

    for (int j = 0; j < ntiles; j++) {
        const float* __restrict__ Kg = g_k + ((size_t)b * SEQ + (size_t)j * ATT_BK) * HD;
        const float* __restrict__ Vg = g_v + ((size_t)b * SEQ + (size_t)j * ATT_BK) * HD;

        __syncthreads();   // all warps done reading previous Ks/Vs/Ps

        // K: RNA-round once at fill (unbiased tf32; MMA truncation is then exact)
#pragma unroll
        for (int t = 0; t < 4; t++) {
            int idx = t * 512 + tid;  // float4 idx over 64x128
            int row = idx >> 5;
            int c4  = (idx & 31) * 4;
            float4 kv = *(const float4*)&Kg[(size_t)row * HD + c4];
            kv.x = rna_tf32(kv.x); kv.y = rna_tf32(kv.y);
            kv.z = rna_tf32(kv.z); kv.w = rna_tf32(kv.w);
            *(float4*)&Ks[row * KSTR + c4] = kv;
        }
        // V: load raw, pre-split into VH (raw) / VL (lo) — exact V
#pragma unroll
        for (int t = 0; t < 4; t++) {
            int idx = t * 512 + tid;
            int row = idx >> 5;
            int c4  = (idx & 31) * 4;
            float4 v = *(const float4*)&Vg[(size_t)row * HD + c4];
            *(float4*)&Vh[row * VSTR + c4] = v;
            float4 l = make_float4(tf32_lo(v.x), tf32_lo(v.y), tf32_lo(v.z), tf32_lo(v.w));
            *(float4*)&Vl[row * VSTR + c4] = l;
        }
        __syncthreads();

        // ---- S = Q . K^T  (warp: 16 rows x 32 cols), exact-Q 2x ----
        float s[4][4];
#pragma unroll
        for (int nf = 0; nf < 4; nf++)
#pragma unroll
            for (int r = 0; r < 4; r++) s[nf][r] = 0.f;

#pragma unroll
        for (int k8 = 0; k8 < 16; k8++) {
            const int k = k8 * 8;
            float a0 = Qs[r0 * QSTR + k + tg];
            float a1 = Qs[(r0 + 8) * QSTR + k + tg];
            float a2 = Qs[r0 * QSTR + k + tg + 4];
            float a3 = Qs[(r0 + 8) * QSTR + k + tg + 4];
            uint32_t ah[4] = {__float_as_uint(a0), __float_as_uint(a1),
                              __float_as_uint(a2), __float_as_uint(a3)};
            uint32_t al[4] = {__float_as_uint(tf32_lo(a0)), __float_as_uint(tf32_lo(a1)),
                              __float_as_uint(tf32_lo(a2)), __float_as_uint(tf32_lo(a3))};
#pragma unroll
            for (int nf = 0; nf < 4; nf++) {
                const int kr = (wn * 32 + nf * 8 + g) * KSTR + k;
                uint32_t bh[2] = {__float_as_uint(Ks[kr + tg]),
                                  __float_as_uint(Ks[kr + tg + 4])};
                mma_tf32(s[nf], ah, bh);
                mma_tf32(s[nf], al, bh);
            }
        }

        // ---- causal mask (only last two kv tiles can intersect the diagonal) ----
        if (j >= 2 * qt) {
            const int colbase = j * ATT_BK + wn * 32;
#pragma unroll
            for (int nf = 0; nf < 4; nf++) {
                int c0 = colbase + nf * 8 + tg * 2;
                if (c0 > rowg)          s[nf][0] = -1e30f;
                if (c0 + 1 > rowg)      s[nf][1] = -1e30f;
                if (c0 > rowg + 8)      s[nf][2] = -1e30f;
                if (c0 + 1 > rowg + 8)  s[nf][3] = -1e30f;
            }
        }

        // ---- local (32-col) row max ----
        float mx0 = -1e30f, mx1 = -1e30f;
#pragma unroll
        for (int nf = 0; nf < 4; nf++) {
            mx0 = fmaxf(mx0, fmaxf(s[nf][0], s[nf][1]));
            mx1 = fmaxf(mx1, fmaxf(s[nf][2], s[nf][3]));
        }
        mx0 = fmaxf(mx0, __shfl_xor_sync(0xffffffffu, mx0, 1));
        mx0 = fmaxf(mx0, __shfl_xor_sync(0xffffffffu, mx0, 2));
        mx1 = fmaxf(mx1, __shfl_xor_sync(0xffffffffu, mx1, 1));
        mx1 = fmaxf(mx1, __shfl_xor_sync(0xffffffffu, mx1, 2));

        // ---- exp relative to local max + local sums ----
        float rs0 = 0.f, rs1 = 0.f;
#pragma unroll
        for (int nf = 0; nf < 4; nf++) {
            s[nf][0] = __expf(s[nf][0] - mx0);
            s[nf][1] = __expf(s[nf][1] - mx0);
            s[nf][2] = __expf(s[nf][2] - mx1);
            s[nf][3] = __expf(s[nf][3] - mx1);
            rs0 += s[nf][0] + s[nf][1];
            rs1 += s[nf][2] + s[nf][3];
        }
        rs0 += __shfl_xor_sync(0xffffffffu, rs0, 1);
        rs0 += __shfl_xor_sync(0xffffffffu, rs0, 2);
        rs1 += __shfl_xor_sync(0xffffffffu, rs1, 1);
        rs1 += __shfl_xor_sync(0xffffffffu, rs1, 2);

        // ---- pairwise merge with the other N-warp ----
        if (tg == 0) {
            Red[r0 * 2 + wn]       = make_float2(mx0, rs0);
            Red[(r0 + 8) * 2 + wn] = make_float2(mx1, rs1);
        }
        asm volatile("bar.sync %0, 64;" :: "r"(1 + wm) : "memory");
        float2 p0 = Red[r0 * 2 + (wn ^ 1)];
        float2 p1 = Red[(r0 + 8) * 2 + (wn ^ 1)];

        float mn0 = fmaxf(m_i[0], fmaxf(mx0, p0.x));
        float mn1 = fmaxf(m_i[1], fmaxf(mx1, p1.x));
        float f0  = __expf(mx0 - mn0);
        float f1  = __expf(mx1 - mn1);
        float al0 = __expf(m_i[0] - mn0);
        float al1 = __expf(m_i[1] - mn1);
        l_i[0] = l_i[0] * al0 + rs0 * f0 + p0.y * __expf(p0.x - mn0);
        l_i[1] = l_i[1] * al1 + rs1 * f1 + p1.y * __expf(p1.x - mn1);
        m_i[0] = mn0;
        m_i[1] = mn1;

#pragma unroll
        for (int nf = 0; nf < 8; nf++) {
            o[nf][0] *= al0; o[nf][1] *= al0;
            o[nf][2] *= al1; o[nf][3] *= al1;
        }

        // ---- stage P (rescaled to global max, RNA-rounded to tf32) ----
#pragma unroll
        for (int nf = 0; nf < 4; nf++) {
            float2 w0 = make_float2(rna_tf32(s[nf][0] * f0), rna_tf32(s[nf][1] * f0));
            float2 w1 = make_float2(rna_tf32(s[nf][2] * f1), rna_tf32(s[nf][3] * f1));
            *(float2*)&Ps[r0 * PSTR + wn * 32 + nf * 8 + tg * 2]       = w0;
            *(float2*)&Ps[(r0 + 8) * PSTR + wn * 32 + nf * 8 + tg * 2] = w1;
        }
        asm volatile("bar.sync %0, 64;" :: "r"(1 + wm) : "memory");

        // ---- O += P . V  (warp: 16 rows x 64 out-cols), exact-V 2x ----
#pragma unroll
        for (int k8 = 0; k8 < 8; k8++) {
            const int k = k8 * 8;
            uint32_t ph[4] = {
                __float_as_uint(Ps[r0 * PSTR + k + tg]),
                __float_as_uint(Ps[(r0 + 8) * PSTR + k + tg]),
                __float_as_uint(Ps[r0 * PSTR + k + tg + 4]),
                __float_as_uint(Ps[(r0 + 8) * PSTR + k + tg + 4])};
#pragma unroll
            for (int nf = 0; nf < 8; nf++) {
                const int col = wn * 64 + nf * 8 + g;
                uint32_t vh[2] = {__float_as_uint(Vh[(k + tg) * VSTR + col]),
                                  __float_as_uint(Vh[(k + tg + 4) * VSTR + col])};
                uint32_t vl[2] = {__float_as_uint(Vl[(k + tg) * VSTR + col]),
                                  __float_as_uint(Vl[(k + tg + 4) * VSTR + col])};
                mma_tf32(o[nf], ph, vh);
                mma_tf32(o[nf], ph, vl);
            }
        }
    }

    // ---- normalize and store ----
    const float inv0 = 1.f / l_i[0];
    const float inv1 = 1.f / l_i[1];
    const size_t orow = (size_t)b * SEQ + (size_t)qt * ATT_BQ + r0;
#pragma unroll
    for (int nf = 0; nf < 8; nf++) {
        const int col = wn * 64 + nf * 8 + tg * 2;
        *(float2*)&out[orow * HD + col]       = make_float2(o[nf][0] * inv0, o[nf][1] * inv0);
        *(float2*)&out[(orow + 8) * HD + col] = make_float2(o[nf][2] * inv1, o[nf][3] * inv1);
    }
}

// ---------------------------------------------------------------------------
extern "C" void kernel_launch(void* const* d_in, const int* in_sizes, int n_in,
                              void* d_out, int out_size)
{
    const float* x  = (const float*)d_in[0];
    const float* wq = (const float*)d_in[1];
    const float* wk = (const float*)d_in[2];
    const float* wv = (const float*)d_in[3];
    float* out = (float*)d_out;

    cudaFuncSetAttribute(proj_mma_kernel,
                         cudaFuncAttributeMaxDynamicSharedMemorySize, PROJ_SMEM);
    cudaFuncSetAttribute(attn_mma_kernel,
                         cudaFuncAttributeMaxDynamicSharedMemorySize, ATT_SMEM);

    dim3 gridP((BSZ * SEQ) / 128, 3);
    proj_mma_kernel<<<gridP, 256, PROJ_SMEM>>>(x, wq, wk, wv);

    dim3 gridA(SEQ / ATT_BQ, BSZ);
    attn_mma_kernel<<<gridA, 512, ATT_SMEM>>>(out);
}